// round 1
// baseline (speedup 1.0000x reference)
#include <cuda_runtime.h>
#include <cuda_bf16.h>
#include <cstdint>

// Problem constants
#define SEQ 4096
#define DIM 1024

// Scratch (device globals; no allocations allowed in kernel_launch)
__device__ float g_qp[SEQ * DIM];
__device__ float g_kp[SEQ * DIM];
__device__ float g_vp[SEQ * DIM];
__device__ float g_att[(size_t)SEQ * SEQ];

using ull = unsigned long long;

__device__ __forceinline__ ull pk2(float x, float y) {
    ull r;
    asm("mov.b64 %0, {%1, %2};" : "=l"(r) : "f"(x), "f"(y));
    return r;
}
__device__ __forceinline__ float2 unpk2(ull p) {
    float2 r;
    asm("mov.b64 {%0, %1}, %2;" : "=f"(r.x), "=f"(r.y) : "l"(p));
    return r;
}
__device__ __forceinline__ void fma2(ull& c, ull a, ull b) {
    // sm_100+ packed fp32 pair FMA: 2 IEEE fp32 FMAs per instruction
    asm("fma.rn.f32x2 %0, %1, %2, %0;" : "+l"(c) : "l"(a), "l"(b));
}

// ---------------------------------------------------------------------------
// Tiled GEMM, 128x128 block tile, BK=16, 256 threads, 8x8 per thread,
// accumulation via packed f32x2 FMA.
//   C[M,Nn] = A[M,K] * op(B) (+ bias[j]) * scale
//   BNT=true : B is [Nn,K] row-major, C[i,j] = sum_k A[i,k]*B[j,k]   (x @ W^T)
//   BNT=false: B is [K,Nn] row-major, C[i,j] = sum_k A[i,k]*B[k,j]
// All dims must be multiples of 128 (K multiple of 16) — true here.
// ---------------------------------------------------------------------------
#define BK 16
#define SSTRIDE 132  // padded shared stride (floats); 132*4 bytes % 16 == 0

template <bool BNT, bool BIAS>
__global__ __launch_bounds__(256)
void gemm_f32x2(const float* __restrict__ A, const float* __restrict__ B,
                const float* __restrict__ bias, float* __restrict__ C,
                int M, int Nn, int K, float scale) {
    __shared__ float As[BK * SSTRIDE];
    __shared__ float Bs[BK * SSTRIDE];

    const int tid = threadIdx.x;
    const int tx = tid & 15;   // 0..15 -> N columns
    const int ty = tid >> 4;   // 0..15 -> M rows
    const int mBase = blockIdx.y * 128;
    const int nBase = blockIdx.x * 128;

    // A-load mapping (K-contiguous rows): 2 float4 per thread per tile
    int aRow[2], aKc[2];
    const float* aPtr[2];
#pragma unroll
    for (int j = 0; j < 2; j++) {
        int idx = tid * 2 + j;          // 0..511
        aRow[j] = idx >> 2;             // 0..127
        aKc[j] = (idx & 3) * 4;         // 0,4,8,12
        aPtr[j] = A + (size_t)(mBase + aRow[j]) * K + aKc[j];
    }

    // B-load mapping
    int bRow[2], bKc[2], bK[2], bNc[2];
    const float* bPtr[2];
#pragma unroll
    for (int j = 0; j < 2; j++) {
        int idx = tid * 2 + j;
        if (BNT) {
            bRow[j] = idx >> 2;
            bKc[j] = (idx & 3) * 4;
            bPtr[j] = B + (size_t)(nBase + bRow[j]) * K + bKc[j];
        } else {
            bK[j] = idx >> 5;           // 0..15
            bNc[j] = (idx & 31) * 4;    // 0..124
            bPtr[j] = B + (size_t)bK[j] * Nn + nBase + bNc[j];
        }
    }

    ull acc[8][4];
#pragma unroll
    for (int m = 0; m < 8; m++)
#pragma unroll
        for (int p = 0; p < 4; p++) acc[m][p] = 0ULL;

    for (int kt = 0; kt < K; kt += BK) {
        // load A tile (transposed into As[k][m])
#pragma unroll
        for (int j = 0; j < 2; j++) {
            float4 v = *reinterpret_cast<const float4*>(aPtr[j] + kt);
            As[(aKc[j] + 0) * SSTRIDE + aRow[j]] = v.x;
            As[(aKc[j] + 1) * SSTRIDE + aRow[j]] = v.y;
            As[(aKc[j] + 2) * SSTRIDE + aRow[j]] = v.z;
            As[(aKc[j] + 3) * SSTRIDE + aRow[j]] = v.w;
        }
        // load B tile into Bs[k][n]
#pragma unroll
        for (int j = 0; j < 2; j++) {
            if (BNT) {
                float4 v = *reinterpret_cast<const float4*>(bPtr[j] + kt);
                Bs[(bKc[j] + 0) * SSTRIDE + bRow[j]] = v.x;
                Bs[(bKc[j] + 1) * SSTRIDE + bRow[j]] = v.y;
                Bs[(bKc[j] + 2) * SSTRIDE + bRow[j]] = v.z;
                Bs[(bKc[j] + 3) * SSTRIDE + bRow[j]] = v.w;
            } else {
                float4 v = *reinterpret_cast<const float4*>(bPtr[j] + (size_t)kt * Nn);
                *reinterpret_cast<float4*>(&Bs[bK[j] * SSTRIDE + bNc[j]]) = v;
            }
        }
        __syncthreads();

#pragma unroll
        for (int k = 0; k < BK; k++) {
            float4 a0 = *reinterpret_cast<const float4*>(&As[k * SSTRIDE + ty * 4]);
            float4 a1 = *reinterpret_cast<const float4*>(&As[k * SSTRIDE + ty * 4 + 64]);
            float4 b0 = *reinterpret_cast<const float4*>(&Bs[k * SSTRIDE + tx * 4]);
            float4 b1 = *reinterpret_cast<const float4*>(&Bs[k * SSTRIDE + tx * 4 + 64]);
            ull bp0 = pk2(b0.x, b0.y);
            ull bp1 = pk2(b0.z, b0.w);
            ull bp2 = pk2(b1.x, b1.y);
            ull bp3 = pk2(b1.z, b1.w);
            float am[8] = {a0.x, a0.y, a0.z, a0.w, a1.x, a1.y, a1.z, a1.w};
#pragma unroll
            for (int m = 0; m < 8; m++) {
                ull pa = pk2(am[m], am[m]);
                fma2(acc[m][0], pa, bp0);
                fma2(acc[m][1], pa, bp1);
                fma2(acc[m][2], pa, bp2);
                fma2(acc[m][3], pa, bp3);
            }
        }
        __syncthreads();
    }

    // epilogue
    float4 bias0 = {0.f, 0.f, 0.f, 0.f}, bias1 = {0.f, 0.f, 0.f, 0.f};
    if (BIAS) {
        bias0 = *reinterpret_cast<const float4*>(&bias[nBase + tx * 4]);
        bias1 = *reinterpret_cast<const float4*>(&bias[nBase + tx * 4 + 64]);
    }
#pragma unroll
    for (int m = 0; m < 8; m++) {
        int r = mBase + ty * 4 + (m & 3) + ((m >> 2) << 6);
        float2 p0 = unpk2(acc[m][0]);
        float2 p1 = unpk2(acc[m][1]);
        float2 p2 = unpk2(acc[m][2]);
        float2 p3 = unpk2(acc[m][3]);
        float4 o0 = {p0.x, p0.y, p1.x, p1.y};
        float4 o1 = {p2.x, p2.y, p3.x, p3.y};
        if (BIAS) {
            o0.x += bias0.x; o0.y += bias0.y; o0.z += bias0.z; o0.w += bias0.w;
            o1.x += bias1.x; o1.y += bias1.y; o1.z += bias1.z; o1.w += bias1.w;
        }
        o0.x *= scale; o0.y *= scale; o0.z *= scale; o0.w *= scale;
        o1.x *= scale; o1.y *= scale; o1.z *= scale; o1.w *= scale;
        *reinterpret_cast<float4*>(&C[(size_t)r * Nn + nBase + tx * 4]) = o0;
        *reinterpret_cast<float4*>(&C[(size_t)r * Nn + nBase + tx * 4 + 64]) = o1;
    }
}

// ---------------------------------------------------------------------------
// Row softmax over 4096 columns, then POST-softmax bias add (in-place on att)
// One block per row, 256 threads, row cached in shared (16 KB).
// ---------------------------------------------------------------------------
__global__ __launch_bounds__(256)
void softmax_bias_kernel(float* __restrict__ att, const float* __restrict__ bias) {
    __shared__ float buf[SEQ];
    __shared__ float red[256];
    const int row = blockIdx.x;
    const int tid = threadIdx.x;
    float* rp = att + (size_t)row * SEQ;
    const float* bp = bias + (size_t)row * SEQ;

    float lmax = -1e30f;
#pragma unroll
    for (int i = 0; i < 4; i++) {
        int idx = (tid + i * 256) * 4;
        float4 v = *reinterpret_cast<const float4*>(rp + idx);
        *reinterpret_cast<float4*>(buf + idx) = v;
        lmax = fmaxf(lmax, fmaxf(fmaxf(v.x, v.y), fmaxf(v.z, v.w)));
    }
    red[tid] = lmax;
    __syncthreads();
    for (int s = 128; s > 0; s >>= 1) {
        if (tid < s) red[tid] = fmaxf(red[tid], red[tid + s]);
        __syncthreads();
    }
    float mx = red[0];
    __syncthreads();

    float lsum = 0.f;
#pragma unroll
    for (int i = 0; i < 4; i++) {
        int idx = (tid + i * 256) * 4;
        float4 v = *reinterpret_cast<float4*>(buf + idx);
        v.x = __expf(v.x - mx);
        v.y = __expf(v.y - mx);
        v.z = __expf(v.z - mx);
        v.w = __expf(v.w - mx);
        *reinterpret_cast<float4*>(buf + idx) = v;
        lsum += v.x + v.y + v.z + v.w;
    }
    red[tid] = lsum;
    __syncthreads();
    for (int s = 128; s > 0; s >>= 1) {
        if (tid < s) red[tid] += red[tid + s];
        __syncthreads();
    }
    float inv = 1.0f / red[0];

#pragma unroll
    for (int i = 0; i < 4; i++) {
        int idx = (tid + i * 256) * 4;
        float4 v = *reinterpret_cast<float4*>(buf + idx);
        float4 b = *reinterpret_cast<const float4*>(bp + idx);
        v.x = v.x * inv + b.x;
        v.y = v.y * inv + b.y;
        v.z = v.z * inv + b.z;
        v.w = v.w * inv + b.w;
        *reinterpret_cast<float4*>(rp + idx) = v;
    }
}

// ---------------------------------------------------------------------------
extern "C" void kernel_launch(void* const* d_in, const int* in_sizes, int n_in,
                              void* d_out, int out_size) {
    const float* q    = (const float*)d_in[0];
    const float* k    = (const float*)d_in[1];
    const float* v    = (const float*)d_in[2];
    const float* bias = (const float*)d_in[3];
    const float* Wq   = (const float*)d_in[4];
    const float* bq   = (const float*)d_in[5];
    const float* Wk   = (const float*)d_in[6];
    const float* bk   = (const float*)d_in[7];
    const float* Wv   = (const float*)d_in[8];
    const float* bv   = (const float*)d_in[9];
    float* out = (float*)d_out;

    float *qp, *kp, *vp, *att;
    cudaGetSymbolAddress((void**)&qp, g_qp);
    cudaGetSymbolAddress((void**)&kp, g_kp);
    cudaGetSymbolAddress((void**)&vp, g_vp);
    cudaGetSymbolAddress((void**)&att, g_att);

    const float scale = 0.03125f;  // 1024^-0.5
    dim3 blk(256);

    // projections: [4096,1024] = X @ W^T + b  (x scale for q)
    dim3 gProj(DIM / 128, SEQ / 128);
    gemm_f32x2<true, true><<<gProj, blk>>>(q, Wq, bq, qp, SEQ, DIM, DIM, scale);
    gemm_f32x2<true, true><<<gProj, blk>>>(k, Wk, bk, kp, SEQ, DIM, DIM, 1.0f);
    gemm_f32x2<true, true><<<gProj, blk>>>(v, Wv, bv, vp, SEQ, DIM, DIM, 1.0f);

    // scores: [4096,4096] = qp @ kp^T
    dim3 gScore(SEQ / 128, SEQ / 128);
    gemm_f32x2<true, false><<<gScore, blk>>>(qp, kp, nullptr, att, SEQ, SEQ, DIM, 1.0f);

    // softmax rows + post-softmax bias (in place)
    softmax_bias_kernel<<<SEQ, blk>>>(att, bias);

    // out: [4096,1024] = att @ vp
    dim3 gOut(DIM / 128, SEQ / 128);
    gemm_f32x2<false, false><<<gOut, blk>>>(att, vp, nullptr, out, SEQ, DIM, SEQ, 1.0f);
}

// round 3
// speedup vs baseline: 2.0027x; 2.0027x over previous
#include <cuda_runtime.h>
#include <cuda_bf16.h>
#include <cstdint>

#define SEQ 4096
#define DIM 1024
typedef __nv_bfloat16 bf16;

// ---------------- scratch (device globals; allocations forbidden) ----------
__device__ bf16 g_qh[SEQ * DIM], g_ql[SEQ * DIM];
__device__ bf16 g_kh[SEQ * DIM], g_kl[SEQ * DIM];
__device__ bf16 g_vh[SEQ * DIM], g_vl[SEQ * DIM];
__device__ bf16 g_Wqh[DIM * DIM], g_Wql[DIM * DIM];
__device__ bf16 g_Wkh[DIM * DIM], g_Wkl[DIM * DIM];
__device__ bf16 g_Wvh[DIM * DIM], g_Wvl[DIM * DIM];
__device__ bf16 g_qph[SEQ * DIM], g_qpl[SEQ * DIM];
__device__ bf16 g_kph[SEQ * DIM], g_kpl[SEQ * DIM];
__device__ bf16 g_vth[DIM * SEQ], g_vtl[DIM * SEQ];   // vp TRANSPOSED [DIM, SEQ]
__device__ float g_att[(size_t)SEQ * SEQ];
__device__ bf16 g_ah[(size_t)SEQ * SEQ], g_al[(size_t)SEQ * SEQ];

// ---------------- helpers ---------------------------------------------------
__device__ __forceinline__ uint32_t smem_u32(const void* p) {
    uint32_t a;
    asm("{ .reg .u64 t; cvta.to.shared.u64 t, %1; cvt.u32.u64 %0, t; }"
        : "=r"(a) : "l"(p));
    return a;
}
__device__ __forceinline__ void cpasync16(uint32_t saddr, const void* gptr) {
    asm volatile("cp.async.cg.shared.global [%0], [%1], 16;"
                 :: "r"(saddr), "l"(gptr) : "memory");
}
#define CP_COMMIT() asm volatile("cp.async.commit_group;" ::: "memory")
#define CP_WAIT1()  asm volatile("cp.async.wait_group 1;" ::: "memory")

#define LDSM_X4(r, addr)                                                        \
    asm volatile("ldmatrix.sync.aligned.m8n8.x4.shared.b16 {%0,%1,%2,%3}, [%4];"\
                 : "=r"((r)[0]), "=r"((r)[1]), "=r"((r)[2]), "=r"((r)[3])       \
                 : "r"(addr))
#define LDSM_X2(r, addr)                                                        \
    asm volatile("ldmatrix.sync.aligned.m8n8.x2.shared.b16 {%0,%1}, [%2];"      \
                 : "=r"((r)[0]), "=r"((r)[1]) : "r"(addr))
#define MMA_BF16(c, a, b)                                                       \
    asm volatile("mma.sync.aligned.m16n8k16.row.col.f32.bf16.bf16.f32 "         \
                 "{%0,%1,%2,%3}, {%4,%5,%6,%7}, {%8,%9}, {%0,%1,%2,%3};"        \
                 : "+f"((c)[0]), "+f"((c)[1]), "+f"((c)[2]), "+f"((c)[3])       \
                 : "r"((a)[0]), "r"((a)[1]), "r"((a)[2]), "r"((a)[3]),          \
                   "r"((b)[0]), "r"((b)[1]))

__device__ __forceinline__ void split1(float x, bf16& h, bf16& l) {
    h = __float2bfloat16_rn(x);
    l = __float2bfloat16_rn(x - __bfloat162float(h));
}

// ---------------- fp32 -> bf16 hi/lo split ----------------------------------
__global__ __launch_bounds__(256)
void split_kernel(const float* __restrict__ x, bf16* __restrict__ h,
                  bf16* __restrict__ l, int n4) {
    int i = blockIdx.x * 256 + threadIdx.x;
    if (i >= n4) return;
    float4 v = reinterpret_cast<const float4*>(x)[i];
    bf16 h0, h1, h2, h3, l0, l1, l2, l3;
    split1(v.x, h0, l0); split1(v.y, h1, l1);
    split1(v.z, h2, l2); split1(v.w, h3, l3);
    __nv_bfloat162* hp = reinterpret_cast<__nv_bfloat162*>(h) + 2 * (size_t)i;
    __nv_bfloat162* lp = reinterpret_cast<__nv_bfloat162*>(l) + 2 * (size_t)i;
    hp[0] = __nv_bfloat162(h0, h1); hp[1] = __nv_bfloat162(h2, h3);
    lp[0] = __nv_bfloat162(l0, l1); lp[1] = __nv_bfloat162(l2, l3);
}

// ---------------- split-bf16 mma.sync GEMM ----------------------------------
// C[M,Nn] = (Ah+Al)[M,K] @ (Bh+Bl)[Nn,K]^T     (both operands K-major)
//   EPI 0: Cf = acc (fp32)
//   EPI 1: (acc+bias)*scale -> split -> Ch/Cl row-major [M,Nn]
//   EPI 2: (acc+bias)       -> split -> Ch/Cl TRANSPOSED [Nn,SEQ]
// Block tile 128x128, BK=32, 256 threads (8 warps, warp tile 64x32), 2-stage
// cp.async pipeline. SMEM tile stride 40 bf16 (80B) -> conflict-free ldmatrix.
#define TSTRIDE 40
#define TILEB (128 * TSTRIDE * 2)        // 10240 B
#define STAGEB (4 * TILEB)               // Ah, Al, Bh, Bl
#define SMEM_SZ (2 * STAGEB)             // 81920 B

template <int EPI>
__global__ __launch_bounds__(256, 1)
void gemm_mma(const bf16* __restrict__ Ah, const bf16* __restrict__ Al,
              const bf16* __restrict__ Bh, const bf16* __restrict__ Bl,
              const float* __restrict__ bias, float* __restrict__ Cf,
              bf16* __restrict__ Ch, bf16* __restrict__ Cl,
              int Nn, int K, float scale) {
    extern __shared__ char smem_raw[];
    const uint32_t sbase = smem_u32(smem_raw);

    const int tid = threadIdx.x;
    const int wid = tid >> 5;
    const int lane = tid & 31;
    const int mBase = blockIdx.y * 128;
    const int nBase = blockIdx.x * 128;
    const int warp_m = (wid & 1) * 64;
    const int warp_n = (wid >> 1) * 32;

    // global load mapping: 2 x 16B per tile per thread
    const int ldRow0 = tid >> 2, ldKc0 = (tid & 3) * 8;
    const int ldRow1 = (tid + 256) >> 2, ldKc1 = ldKc0;
    const uint32_t sOff0 = ldRow0 * (TSTRIDE * 2) + ldKc0 * 2;
    const uint32_t sOff1 = ldRow1 * (TSTRIDE * 2) + ldKc1 * 2;

    const bf16* gA[2] = {Ah + (size_t)mBase * K, Al + (size_t)mBase * K};
    const bf16* gB[2] = {Bh + (size_t)nBase * K, Bl + (size_t)nBase * K};

    // ldmatrix per-thread byte offsets within a tile
    const uint32_t aOff = (warp_m + (lane & 15)) * (TSTRIDE * 2) + (lane >> 4) * 16;
    const int bl = lane & 15;
    const uint32_t bOff = (warp_n + (bl & 7)) * (TSTRIDE * 2) + (bl >> 3) * 16;

    float acc[4][4][4];
#pragma unroll
    for (int i = 0; i < 4; i++)
#pragma unroll
        for (int j = 0; j < 4; j++)
#pragma unroll
            for (int p = 0; p < 4; p++) acc[i][j][p] = 0.f;

    const int NIT = K >> 5;   // K / 32

    // prologue: stage 0
    {
        const uint32_t sb = sbase;
#pragma unroll
        for (int t = 0; t < 2; t++) {
            cpasync16(sb + t * TILEB + sOff0, gA[t] + (size_t)ldRow0 * K + ldKc0);
            cpasync16(sb + t * TILEB + sOff1, gA[t] + (size_t)ldRow1 * K + ldKc1);
            cpasync16(sb + (2 + t) * TILEB + sOff0, gB[t] + (size_t)ldRow0 * K + ldKc0);
            cpasync16(sb + (2 + t) * TILEB + sOff1, gB[t] + (size_t)ldRow1 * K + ldKc1);
        }
        CP_COMMIT();
    }

    for (int it = 0; it < NIT; it++) {
        const uint32_t cb = sbase + (it & 1) * STAGEB;
        if (it + 1 < NIT) {
            const uint32_t nb = sbase + ((it + 1) & 1) * STAGEB;
            const int kt = (it + 1) * 32;
#pragma unroll
            for (int t = 0; t < 2; t++) {
                cpasync16(nb + t * TILEB + sOff0, gA[t] + (size_t)ldRow0 * K + kt + ldKc0);
                cpasync16(nb + t * TILEB + sOff1, gA[t] + (size_t)ldRow1 * K + kt + ldKc1);
                cpasync16(nb + (2 + t) * TILEB + sOff0, gB[t] + (size_t)ldRow0 * K + kt + ldKc0);
                cpasync16(nb + (2 + t) * TILEB + sOff1, gB[t] + (size_t)ldRow1 * K + kt + ldKc1);
            }
        }
        CP_COMMIT();
        CP_WAIT1();
        __syncthreads();

#pragma unroll
        for (int ks = 0; ks < 2; ks++) {
            uint32_t ah[4][4], al[4][4], bh[4][2], blr[4][2];
            const uint32_t abase = cb + aOff + ks * 32;
            const uint32_t bbase = cb + bOff + ks * 32;
#pragma unroll
            for (int mf = 0; mf < 4; mf++) {
                LDSM_X4(ah[mf], abase + 0 * TILEB + mf * (16 * TSTRIDE * 2));
                LDSM_X4(al[mf], abase + 1 * TILEB + mf * (16 * TSTRIDE * 2));
            }
#pragma unroll
            for (int nf = 0; nf < 4; nf++) {
                LDSM_X2(bh[nf], bbase + 2 * TILEB + nf * (8 * TSTRIDE * 2));
                LDSM_X2(blr[nf], bbase + 3 * TILEB + nf * (8 * TSTRIDE * 2));
            }
#pragma unroll
            for (int mf = 0; mf < 4; mf++)
#pragma unroll
                for (int nf = 0; nf < 4; nf++) MMA_BF16(acc[mf][nf], ah[mf], bh[nf]);
#pragma unroll
            for (int mf = 0; mf < 4; mf++)
#pragma unroll
                for (int nf = 0; nf < 4; nf++) MMA_BF16(acc[mf][nf], al[mf], bh[nf]);
#pragma unroll
            for (int mf = 0; mf < 4; mf++)
#pragma unroll
                for (int nf = 0; nf < 4; nf++) MMA_BF16(acc[mf][nf], ah[mf], blr[nf]);
        }
        __syncthreads();
    }

    // ------------- epilogue -------------
    if (EPI == 0) {
#pragma unroll
        for (int mf = 0; mf < 4; mf++)
#pragma unroll
            for (int nf = 0; nf < 4; nf++) {
                int row = mBase + warp_m + mf * 16 + (lane >> 2);
                int col = nBase + warp_n + nf * 8 + 2 * (lane & 3);
                float2 v0 = {acc[mf][nf][0], acc[mf][nf][1]};
                float2 v1 = {acc[mf][nf][2], acc[mf][nf][3]};
                *reinterpret_cast<float2*>(&Cf[(size_t)row * Nn + col]) = v0;
                *reinterpret_cast<float2*>(&Cf[(size_t)(row + 8) * Nn + col]) = v1;
            }
    } else if (EPI == 1) {
#pragma unroll
        for (int mf = 0; mf < 4; mf++)
#pragma unroll
            for (int nf = 0; nf < 4; nf++) {
                int row = mBase + warp_m + mf * 16 + (lane >> 2);
                int col = nBase + warp_n + nf * 8 + 2 * (lane & 3);
                float b0 = bias[col], b1 = bias[col + 1];
                float x0 = (acc[mf][nf][0] + b0) * scale;
                float x1 = (acc[mf][nf][1] + b1) * scale;
                float x2 = (acc[mf][nf][2] + b0) * scale;
                float x3 = (acc[mf][nf][3] + b1) * scale;
                bf16 h0, l0, h1, l1, h2, l2, h3, l3;
                split1(x0, h0, l0); split1(x1, h1, l1);
                split1(x2, h2, l2); split1(x3, h3, l3);
                *reinterpret_cast<__nv_bfloat162*>(&Ch[(size_t)row * Nn + col]) =
                    __nv_bfloat162(h0, h1);
                *reinterpret_cast<__nv_bfloat162*>(&Cl[(size_t)row * Nn + col]) =
                    __nv_bfloat162(l0, l1);
                *reinterpret_cast<__nv_bfloat162*>(&Ch[(size_t)(row + 8) * Nn + col]) =
                    __nv_bfloat162(h2, h3);
                *reinterpret_cast<__nv_bfloat162*>(&Cl[(size_t)(row + 8) * Nn + col]) =
                    __nv_bfloat162(l2, l3);
            }
    } else {
        // transpose via SMEM: sb[col][row], then coalesced split-store
        float* sb = reinterpret_cast<float*>(smem_raw);
        __syncthreads();
#pragma unroll
        for (int mf = 0; mf < 4; mf++)
#pragma unroll
            for (int nf = 0; nf < 4; nf++) {
                int rl = warp_m + mf * 16 + (lane >> 2);
                int cl = warp_n + nf * 8 + 2 * (lane & 3);
                float b0 = bias[nBase + cl], b1 = bias[nBase + cl + 1];
                sb[cl * 129 + rl] = acc[mf][nf][0] + b0;
                sb[(cl + 1) * 129 + rl] = acc[mf][nf][1] + b1;
                sb[cl * 129 + rl + 8] = acc[mf][nf][2] + b0;
                sb[(cl + 1) * 129 + rl + 8] = acc[mf][nf][3] + b1;
            }
        __syncthreads();
        const int col = tid >> 1;
        const int half = (tid & 1) * 64;
        size_t base = (size_t)(nBase + col) * SEQ + mBase + half;
#pragma unroll
        for (int r = 0; r < 64; r += 2) {
            float x0 = sb[col * 129 + half + r];
            float x1 = sb[col * 129 + half + r + 1];
            bf16 h0, l0, h1, l1;
            split1(x0, h0, l0); split1(x1, h1, l1);
            *reinterpret_cast<__nv_bfloat162*>(&Ch[base + r]) = __nv_bfloat162(h0, h1);
            *reinterpret_cast<__nv_bfloat162*>(&Cl[base + r]) = __nv_bfloat162(l0, l1);
        }
    }
}

// ---------------- softmax + post-softmax bias -> bf16 hi/lo -----------------
__global__ __launch_bounds__(256)
void softmax_bias_split(const float* __restrict__ att, const float* __restrict__ bias,
                        bf16* __restrict__ ah, bf16* __restrict__ al) {
    __shared__ float buf[SEQ];
    __shared__ float red[256];
    const int row = blockIdx.x;
    const int tid = threadIdx.x;
    const float* rp = att + (size_t)row * SEQ;
    const float* bp = bias + (size_t)row * SEQ;

    float lmax = -1e30f;
#pragma unroll
    for (int i = 0; i < 4; i++) {
        int idx = (tid + i * 256) * 4;
        float4 v = *reinterpret_cast<const float4*>(rp + idx);
        *reinterpret_cast<float4*>(buf + idx) = v;
        lmax = fmaxf(lmax, fmaxf(fmaxf(v.x, v.y), fmaxf(v.z, v.w)));
    }
    red[tid] = lmax;
    __syncthreads();
    for (int s = 128; s > 0; s >>= 1) {
        if (tid < s) red[tid] = fmaxf(red[tid], red[tid + s]);
        __syncthreads();
    }
    float mx = red[0];
    __syncthreads();

    float lsum = 0.f;
#pragma unroll
    for (int i = 0; i < 4; i++) {
        int idx = (tid + i * 256) * 4;
        float4 v = *reinterpret_cast<float4*>(buf + idx);
        v.x = __expf(v.x - mx); v.y = __expf(v.y - mx);
        v.z = __expf(v.z - mx); v.w = __expf(v.w - mx);
        *reinterpret_cast<float4*>(buf + idx) = v;
        lsum += v.x + v.y + v.z + v.w;
    }
    red[tid] = lsum;
    __syncthreads();
    for (int s = 128; s > 0; s >>= 1) {
        if (tid < s) red[tid] += red[tid + s];
        __syncthreads();
    }
    float inv = 1.0f / red[0];

#pragma unroll
    for (int i = 0; i < 4; i++) {
        int idx = (tid + i * 256) * 4;
        float4 v = *reinterpret_cast<float4*>(buf + idx);
        float4 b = *reinterpret_cast<const float4*>(bp + idx);
        float x0 = v.x * inv + b.x, x1 = v.y * inv + b.y;
        float x2 = v.z * inv + b.z, x3 = v.w * inv + b.w;
        bf16 h0, l0, h1, l1, h2, l2, h3, l3;
        split1(x0, h0, l0); split1(x1, h1, l1);
        split1(x2, h2, l2); split1(x3, h3, l3);
        size_t o = (size_t)row * SEQ + idx;
        __nv_bfloat162 hv[2] = {{h0, h1}, {h2, h3}};
        __nv_bfloat162 lv[2] = {{l0, l1}, {l2, l3}};
        *reinterpret_cast<uint2*>(ah + o) = *reinterpret_cast<uint2*>(hv);
        *reinterpret_cast<uint2*>(al + o) = *reinterpret_cast<uint2*>(lv);
    }
}

// ---------------------------------------------------------------------------
extern "C" void kernel_launch(void* const* d_in, const int* in_sizes, int n_in,
                              void* d_out, int out_size) {
    const float* q = (const float*)d_in[0];
    const float* k = (const float*)d_in[1];
    const float* v = (const float*)d_in[2];
    const float* bias = (const float*)d_in[3];
    const float* Wq = (const float*)d_in[4];
    const float* bq = (const float*)d_in[5];
    const float* Wk = (const float*)d_in[6];
    const float* bk = (const float*)d_in[7];
    const float* Wv = (const float*)d_in[8];
    const float* bv = (const float*)d_in[9];
    float* out = (float*)d_out;

    bf16 *qh, *ql, *kh, *kl, *vh, *vl, *Wqh, *Wql, *Wkh, *Wkl, *Wvh, *Wvl;
    bf16 *qph, *qpl, *kph, *kpl, *vth, *vtl, *ah, *al;
    float* att;
    cudaGetSymbolAddress((void**)&qh, g_qh);   cudaGetSymbolAddress((void**)&ql, g_ql);
    cudaGetSymbolAddress((void**)&kh, g_kh);   cudaGetSymbolAddress((void**)&kl, g_kl);
    cudaGetSymbolAddress((void**)&vh, g_vh);   cudaGetSymbolAddress((void**)&vl, g_vl);
    cudaGetSymbolAddress((void**)&Wqh, g_Wqh); cudaGetSymbolAddress((void**)&Wql, g_Wql);
    cudaGetSymbolAddress((void**)&Wkh, g_Wkh); cudaGetSymbolAddress((void**)&Wkl, g_Wkl);
    cudaGetSymbolAddress((void**)&Wvh, g_Wvh); cudaGetSymbolAddress((void**)&Wvl, g_Wvl);
    cudaGetSymbolAddress((void**)&qph, g_qph); cudaGetSymbolAddress((void**)&qpl, g_qpl);
    cudaGetSymbolAddress((void**)&kph, g_kph); cudaGetSymbolAddress((void**)&kpl, g_kpl);
    cudaGetSymbolAddress((void**)&vth, g_vth); cudaGetSymbolAddress((void**)&vtl, g_vtl);
    cudaGetSymbolAddress((void**)&ah, g_ah);   cudaGetSymbolAddress((void**)&al, g_al);
    cudaGetSymbolAddress((void**)&att, g_att);

    cudaFuncSetAttribute(gemm_mma<0>, cudaFuncAttributeMaxDynamicSharedMemorySize, SMEM_SZ);
    cudaFuncSetAttribute(gemm_mma<1>, cudaFuncAttributeMaxDynamicSharedMemorySize, SMEM_SZ);
    cudaFuncSetAttribute(gemm_mma<2>, cudaFuncAttributeMaxDynamicSharedMemorySize, SMEM_SZ);

    const float scale = 0.03125f;  // 1024^-0.5
    dim3 blk(256);

    // fp32 -> bf16 hi/lo conversions
    split_kernel<<<SEQ * DIM / 4 / 256, blk>>>(q, qh, ql, SEQ * DIM / 4);
    split_kernel<<<SEQ * DIM / 4 / 256, blk>>>(k, kh, kl, SEQ * DIM / 4);
    split_kernel<<<SEQ * DIM / 4 / 256, blk>>>(v, vh, vl, SEQ * DIM / 4);
    split_kernel<<<DIM * DIM / 4 / 256, blk>>>(Wq, Wqh, Wql, DIM * DIM / 4);
    split_kernel<<<DIM * DIM / 4 / 256, blk>>>(Wk, Wkh, Wkl, DIM * DIM / 4);
    split_kernel<<<DIM * DIM / 4 / 256, blk>>>(Wv, Wvh, Wvl, DIM * DIM / 4);

    // projections
    dim3 gProj(DIM / 128, SEQ / 128);
    gemm_mma<1><<<gProj, blk, SMEM_SZ>>>(qh, ql, Wqh, Wql, bq, nullptr, qph, qpl,
                                         DIM, DIM, scale);
    gemm_mma<1><<<gProj, blk, SMEM_SZ>>>(kh, kl, Wkh, Wkl, bk, nullptr, kph, kpl,
                                         DIM, DIM, 1.0f);
    gemm_mma<2><<<gProj, blk, SMEM_SZ>>>(vh, vl, Wvh, Wvl, bv, nullptr, vth, vtl,
                                         DIM, DIM, 1.0f);

    // scores = qp @ kp^T  (fp32 out)
    dim3 gScore(SEQ / 128, SEQ / 128);
    gemm_mma<0><<<gScore, blk, SMEM_SZ>>>(qph, qpl, kph, kpl, nullptr, att,
                                          nullptr, nullptr, SEQ, DIM, 1.0f);

    // softmax + bias -> att hi/lo
    softmax_bias_split<<<SEQ, blk>>>(att, bias, ah, al);

    // out = att @ vp  (vp accessed as vpT, K-major)
    dim3 gOut(DIM / 128, SEQ / 128);
    gemm_mma<0><<<gOut, blk, SMEM_SZ>>>(ah, al, vth, vtl, nullptr, out,
                                        nullptr, nullptr, DIM, SEQ, 1.0f);
}

// round 4
// speedup vs baseline: 2.6904x; 1.3434x over previous
#include <cuda_runtime.h>
#include <cuda_fp16.h>
#include <cstdint>

#define SEQ 4096
#define DIM 1024
typedef __half fp16;

// ---------------- scratch (device globals; allocations forbidden) ----------
__device__ fp16 g_qh[SEQ * DIM], g_ql[SEQ * DIM];
__device__ fp16 g_kh[SEQ * DIM], g_kl[SEQ * DIM];
__device__ fp16 g_vh[SEQ * DIM], g_vl[SEQ * DIM];
__device__ fp16 g_Wqh[DIM * DIM], g_Wql[DIM * DIM];
__device__ fp16 g_Wkh[DIM * DIM], g_Wkl[DIM * DIM];
__device__ fp16 g_Wvh[DIM * DIM], g_Wvl[DIM * DIM];
__device__ fp16 g_qph[SEQ * DIM], g_qpl[SEQ * DIM];
__device__ fp16 g_kph[SEQ * DIM], g_kpl[SEQ * DIM];   // kpl written, unused
__device__ fp16 g_vth[DIM * SEQ], g_vtl[DIM * SEQ];   // vp TRANSPOSED [DIM, SEQ]
__device__ float g_att[(size_t)SEQ * SEQ];
__device__ fp16 g_ah[(size_t)SEQ * SEQ], g_al[(size_t)SEQ * SEQ];

// ---------------- helpers ---------------------------------------------------
__device__ __forceinline__ uint32_t smem_u32(const void* p) {
    uint32_t a;
    asm("{ .reg .u64 t; cvta.to.shared.u64 t, %1; cvt.u32.u64 %0, t; }"
        : "=r"(a) : "l"(p));
    return a;
}
__device__ __forceinline__ void cpasync16(uint32_t saddr, const void* gptr) {
    asm volatile("cp.async.cg.shared.global [%0], [%1], 16;"
                 :: "r"(saddr), "l"(gptr) : "memory");
}
#define CP_COMMIT() asm volatile("cp.async.commit_group;" ::: "memory")
#define CP_WAIT1()  asm volatile("cp.async.wait_group 1;" ::: "memory")

#define LDSM_X4(r, addr)                                                        \
    asm volatile("ldmatrix.sync.aligned.m8n8.x4.shared.b16 {%0,%1,%2,%3}, [%4];"\
                 : "=r"((r)[0]), "=r"((r)[1]), "=r"((r)[2]), "=r"((r)[3])       \
                 : "r"(addr))
#define LDSM_X2(r, addr)                                                        \
    asm volatile("ldmatrix.sync.aligned.m8n8.x2.shared.b16 {%0,%1}, [%2];"      \
                 : "=r"((r)[0]), "=r"((r)[1]) : "r"(addr))
#define MMA_F16(c, a, b)                                                        \
    asm volatile("mma.sync.aligned.m16n8k16.row.col.f32.f16.f16.f32 "           \
                 "{%0,%1,%2,%3}, {%4,%5,%6,%7}, {%8,%9}, {%0,%1,%2,%3};"        \
                 : "+f"((c)[0]), "+f"((c)[1]), "+f"((c)[2]), "+f"((c)[3])       \
                 : "r"((a)[0]), "r"((a)[1]), "r"((a)[2]), "r"((a)[3]),          \
                   "r"((b)[0]), "r"((b)[1]))

__device__ __forceinline__ void split1(float x, fp16& h, fp16& l) {
    h = __float2half_rn(x);
    l = __float2half_rn(x - __half2float(h));
}

// ---------------- fp32 -> fp16 hi/lo split ----------------------------------
__global__ __launch_bounds__(256)
void split_kernel(const float* __restrict__ x, fp16* __restrict__ h,
                  fp16* __restrict__ l, int n4) {
    int i = blockIdx.x * 256 + threadIdx.x;
    if (i >= n4) return;
    float4 v = reinterpret_cast<const float4*>(x)[i];
    fp16 h0, h1, h2, h3, l0, l1, l2, l3;
    split1(v.x, h0, l0); split1(v.y, h1, l1);
    split1(v.z, h2, l2); split1(v.w, h3, l3);
    __half2* hp = reinterpret_cast<__half2*>(h) + 2 * (size_t)i;
    __half2* lp = reinterpret_cast<__half2*>(l) + 2 * (size_t)i;
    hp[0] = __half2(h0, h1); hp[1] = __half2(h2, h3);
    lp[0] = __half2(l0, l1); lp[1] = __half2(l2, l3);
}

// ---------------- split-fp16 mma.sync GEMM ----------------------------------
// C[M,Nn] = (Ah+Al)[M,K] @ op(B)[Nn,K]^T  (K-major operands)
//   TERMS==2: acc = Ah·Bh + Al·Bh           (B = plain fp16)
//   TERMS==3: acc = Ah·Bh + Al·Bh + Ah·Bl   (B split fp16)
//   EPI 0: Cf = acc (fp32)
//   EPI 1: (acc+bias)*scale -> split -> Ch/Cl row-major [M,Nn]
//   EPI 2: (acc+bias)       -> split -> Ch/Cl TRANSPOSED [Nn,SEQ]
// 128x128 tile, BK=32, 256 thr (8 warps, 64x32 warp tile), 3-stage cp.async.
#define TSTRIDE 40
#define TILEB (128 * TSTRIDE * 2)            // 10240 B
#define STAGEB(T) (((T) + 1) * TILEB)
#define SMEMSZ(T) (3 * STAGEB(T))

template <int EPI, int TERMS>
__global__ __launch_bounds__(256, 1)
void gemm_mma(const fp16* __restrict__ Ah, const fp16* __restrict__ Al,
              const fp16* __restrict__ Bh, const fp16* __restrict__ Bl,
              const float* __restrict__ bias, float* __restrict__ Cf,
              fp16* __restrict__ Ch, fp16* __restrict__ Cl,
              int Nn, int K, float scale) {
    extern __shared__ char smem_raw[];
    const uint32_t sbase = smem_u32(smem_raw);
    constexpr int NT = TERMS + 1;              // tiles per stage
    constexpr uint32_t STB = STAGEB(TERMS);

    const int tid = threadIdx.x;
    const int wid = tid >> 5;
    const int lane = tid & 31;
    const int mBase = blockIdx.y * 128;
    const int nBase = blockIdx.x * 128;
    const int warp_m = (wid & 1) * 64;
    const int warp_n = (wid >> 1) * 32;

    // global->smem mapping: 2 x 16B per tile per thread
    const int ldRow0 = tid >> 2, ldKc = (tid & 3) * 8;
    const int ldRow1 = ldRow0 + 64;
    const uint32_t sOff0 = ldRow0 * (TSTRIDE * 2) + ldKc * 2;
    const uint32_t sOff1 = ldRow1 * (TSTRIDE * 2) + ldKc * 2;

    const fp16* gT[4];
    gT[0] = Ah + (size_t)mBase * K;
    gT[1] = Al + (size_t)mBase * K;
    gT[2] = Bh + (size_t)nBase * K;
    gT[3] = (TERMS == 3) ? Bl + (size_t)nBase * K : gT[2];

    // ldmatrix per-thread byte offsets within a tile
    const uint32_t aOff = (warp_m + (lane & 15)) * (TSTRIDE * 2) + (lane >> 4) * 16;
    const int bl16 = lane & 15;
    const uint32_t bOff = (warp_n + (bl16 & 7)) * (TSTRIDE * 2) + (bl16 >> 3) * 16;

    float acc[4][4][4];
#pragma unroll
    for (int i = 0; i < 4; i++)
#pragma unroll
        for (int j = 0; j < 4; j++)
#pragma unroll
            for (int p = 0; p < 4; p++) acc[i][j][p] = 0.f;

    const int NIT = K >> 5;

    // prologue: stages 0,1
#pragma unroll
    for (int s = 0; s < 2; s++) {
        const uint32_t nb = sbase + s * STB;
        const int kt = s * 32;
#pragma unroll
        for (int t = 0; t < NT; t++) {
            cpasync16(nb + t * TILEB + sOff0, gT[t] + (size_t)ldRow0 * K + kt + ldKc);
            cpasync16(nb + t * TILEB + sOff1, gT[t] + (size_t)ldRow1 * K + kt + ldKc);
        }
        CP_COMMIT();
    }

    int stage = 0;
    for (int it = 0; it < NIT; it++) {
        CP_WAIT1();
        __syncthreads();

        // issue stage it+2 (overlaps with compute below)
        if (it + 2 < NIT) {
            int ns = stage + 2; if (ns >= 3) ns -= 3;
            const uint32_t nb = sbase + ns * STB;
            const int kt = (it + 2) * 32;
#pragma unroll
            for (int t = 0; t < NT; t++) {
                cpasync16(nb + t * TILEB + sOff0, gT[t] + (size_t)ldRow0 * K + kt + ldKc);
                cpasync16(nb + t * TILEB + sOff1, gT[t] + (size_t)ldRow1 * K + kt + ldKc);
            }
        }
        CP_COMMIT();

        const uint32_t cb = sbase + stage * STB;
#pragma unroll
        for (int ks = 0; ks < 2; ks++) {
            uint32_t af[4][4], alf[4][4], bf[4][2], blf[4][2];
            const uint32_t abase = cb + aOff + ks * 32;
            const uint32_t bbase = cb + bOff + ks * 32;
#pragma unroll
            for (int mf = 0; mf < 4; mf++) {
                LDSM_X4(af[mf], abase + 0 * TILEB + mf * (16 * TSTRIDE * 2));
                LDSM_X4(alf[mf], abase + 1 * TILEB + mf * (16 * TSTRIDE * 2));
            }
#pragma unroll
            for (int nf = 0; nf < 4; nf++) {
                LDSM_X2(bf[nf], bbase + 2 * TILEB + nf * (8 * TSTRIDE * 2));
                if (TERMS == 3)
                    LDSM_X2(blf[nf], bbase + 3 * TILEB + nf * (8 * TSTRIDE * 2));
            }
#pragma unroll
            for (int mf = 0; mf < 4; mf++)
#pragma unroll
                for (int nf = 0; nf < 4; nf++) MMA_F16(acc[mf][nf], af[mf], bf[nf]);
#pragma unroll
            for (int mf = 0; mf < 4; mf++)
#pragma unroll
                for (int nf = 0; nf < 4; nf++) MMA_F16(acc[mf][nf], alf[mf], bf[nf]);
            if (TERMS == 3) {
#pragma unroll
                for (int mf = 0; mf < 4; mf++)
#pragma unroll
                    for (int nf = 0; nf < 4; nf++) MMA_F16(acc[mf][nf], af[mf], blf[nf]);
            }
        }
        if (++stage == 3) stage = 0;
    }

    // ------------- epilogue -------------
    if (EPI == 0) {
#pragma unroll
        for (int mf = 0; mf < 4; mf++)
#pragma unroll
            for (int nf = 0; nf < 4; nf++) {
                int row = mBase + warp_m + mf * 16 + (lane >> 2);
                int col = nBase + warp_n + nf * 8 + 2 * (lane & 3);
                float2 v0 = {acc[mf][nf][0], acc[mf][nf][1]};
                float2 v1 = {acc[mf][nf][2], acc[mf][nf][3]};
                *reinterpret_cast<float2*>(&Cf[(size_t)row * Nn + col]) = v0;
                *reinterpret_cast<float2*>(&Cf[(size_t)(row + 8) * Nn + col]) = v1;
            }
    } else if (EPI == 1) {
#pragma unroll
        for (int mf = 0; mf < 4; mf++)
#pragma unroll
            for (int nf = 0; nf < 4; nf++) {
                int row = mBase + warp_m + mf * 16 + (lane >> 2);
                int col = nBase + warp_n + nf * 8 + 2 * (lane & 3);
                float b0 = bias[col], b1 = bias[col + 1];
                float x0 = (acc[mf][nf][0] + b0) * scale;
                float x1 = (acc[mf][nf][1] + b1) * scale;
                float x2 = (acc[mf][nf][2] + b0) * scale;
                float x3 = (acc[mf][nf][3] + b1) * scale;
                fp16 h0, l0, h1, l1, h2, l2, h3, l3;
                split1(x0, h0, l0); split1(x1, h1, l1);
                split1(x2, h2, l2); split1(x3, h3, l3);
                *reinterpret_cast<__half2*>(&Ch[(size_t)row * Nn + col]) = __half2(h0, h1);
                *reinterpret_cast<__half2*>(&Cl[(size_t)row * Nn + col]) = __half2(l0, l1);
                *reinterpret_cast<__half2*>(&Ch[(size_t)(row + 8) * Nn + col]) = __half2(h2, h3);
                *reinterpret_cast<__half2*>(&Cl[(size_t)(row + 8) * Nn + col]) = __half2(l2, l3);
            }
    } else {
        // transpose via SMEM then coalesced split-store (Ch/Cl are [Nn, SEQ])
        float* sb = reinterpret_cast<float*>(smem_raw);
        __syncthreads();
#pragma unroll
        for (int mf = 0; mf < 4; mf++)
#pragma unroll
            for (int nf = 0; nf < 4; nf++) {
                int rl = warp_m + mf * 16 + (lane >> 2);
                int cl = warp_n + nf * 8 + 2 * (lane & 3);
                float b0 = bias[nBase + cl], b1 = bias[nBase + cl + 1];
                sb[cl * 129 + rl] = acc[mf][nf][0] + b0;
                sb[(cl + 1) * 129 + rl] = acc[mf][nf][1] + b1;
                sb[cl * 129 + rl + 8] = acc[mf][nf][2] + b0;
                sb[(cl + 1) * 129 + rl + 8] = acc[mf][nf][3] + b1;
            }
        __syncthreads();
        const int col = tid >> 1;
        const int half = (tid & 1) * 64;
        size_t base = (size_t)(nBase + col) * SEQ + mBase + half;
#pragma unroll
        for (int r = 0; r < 64; r += 2) {
            float x0 = sb[col * 129 + half + r];
            float x1 = sb[col * 129 + half + r + 1];
            fp16 h0, l0, h1, l1;
            split1(x0, h0, l0); split1(x1, h1, l1);
            *reinterpret_cast<__half2*>(&Ch[base + r]) = __half2(h0, h1);
            *reinterpret_cast<__half2*>(&Cl[base + r]) = __half2(l0, l1);
        }
    }
}

// --------- softmax(scale*scores) + post-softmax bias -> fp16 hi/lo ----------
__global__ __launch_bounds__(256)
void softmax_bias_split(const float* __restrict__ att, const float* __restrict__ bias,
                        fp16* __restrict__ ah, fp16* __restrict__ al, float scale) {
    __shared__ float buf[SEQ];
    __shared__ float red[256];
    const int row = blockIdx.x;
    const int tid = threadIdx.x;
    const float* rp = att + (size_t)row * SEQ;
    const float* bp = bias + (size_t)row * SEQ;

    float lmax = -1e30f;
#pragma unroll
    for (int i = 0; i < 4; i++) {
        int idx = (tid + i * 256) * 4;
        float4 v = *reinterpret_cast<const float4*>(rp + idx);
        v.x *= scale; v.y *= scale; v.z *= scale; v.w *= scale;
        *reinterpret_cast<float4*>(buf + idx) = v;
        lmax = fmaxf(lmax, fmaxf(fmaxf(v.x, v.y), fmaxf(v.z, v.w)));
    }
    red[tid] = lmax;
    __syncthreads();
    for (int s = 128; s > 0; s >>= 1) {
        if (tid < s) red[tid] = fmaxf(red[tid], red[tid + s]);
        __syncthreads();
    }
    float mx = red[0];
    __syncthreads();

    float lsum = 0.f;
#pragma unroll
    for (int i = 0; i < 4; i++) {
        int idx = (tid + i * 256) * 4;
        float4 v = *reinterpret_cast<float4*>(buf + idx);
        v.x = __expf(v.x - mx); v.y = __expf(v.y - mx);
        v.z = __expf(v.z - mx); v.w = __expf(v.w - mx);
        *reinterpret_cast<float4*>(buf + idx) = v;
        lsum += v.x + v.y + v.z + v.w;
    }
    red[tid] = lsum;
    __syncthreads();
    for (int s = 128; s > 0; s >>= 1) {
        if (tid < s) red[tid] += red[tid + s];
        __syncthreads();
    }
    float inv = 1.0f / red[0];

#pragma unroll
    for (int i = 0; i < 4; i++) {
        int idx = (tid + i * 256) * 4;
        float4 v = *reinterpret_cast<float4*>(buf + idx);
        float4 b = *reinterpret_cast<const float4*>(bp + idx);
        float x0 = v.x * inv + b.x, x1 = v.y * inv + b.y;
        float x2 = v.z * inv + b.z, x3 = v.w * inv + b.w;
        fp16 h0, l0, h1, l1, h2, l2, h3, l3;
        split1(x0, h0, l0); split1(x1, h1, l1);
        split1(x2, h2, l2); split1(x3, h3, l3);
        size_t o = (size_t)row * SEQ + idx;
        __half2 hv[2] = {{h0, h1}, {h2, h3}};
        __half2 lv[2] = {{l0, l1}, {l2, l3}};
        *reinterpret_cast<uint2*>(ah + o) = *reinterpret_cast<uint2*>(hv);
        *reinterpret_cast<uint2*>(al + o) = *reinterpret_cast<uint2*>(lv);
    }
}

// ---------------------------------------------------------------------------
extern "C" void kernel_launch(void* const* d_in, const int* in_sizes, int n_in,
                              void* d_out, int out_size) {
    const float* q = (const float*)d_in[0];
    const float* k = (const float*)d_in[1];
    const float* v = (const float*)d_in[2];
    const float* bias = (const float*)d_in[3];
    const float* Wq = (const float*)d_in[4];
    const float* bq = (const float*)d_in[5];
    const float* Wk = (const float*)d_in[6];
    const float* bk = (const float*)d_in[7];
    const float* Wv = (const float*)d_in[8];
    const float* bv = (const float*)d_in[9];
    float* out = (float*)d_out;

    fp16 *qh, *ql, *kh, *kl, *vh, *vl, *Wqh, *Wql, *Wkh, *Wkl, *Wvh, *Wvl;
    fp16 *qph, *qpl, *kph, *kpl, *vth, *vtl, *ah, *al;
    float* att;
    cudaGetSymbolAddress((void**)&qh, g_qh);   cudaGetSymbolAddress((void**)&ql, g_ql);
    cudaGetSymbolAddress((void**)&kh, g_kh);   cudaGetSymbolAddress((void**)&kl, g_kl);
    cudaGetSymbolAddress((void**)&vh, g_vh);   cudaGetSymbolAddress((void**)&vl, g_vl);
    cudaGetSymbolAddress((void**)&Wqh, g_Wqh); cudaGetSymbolAddress((void**)&Wql, g_Wql);
    cudaGetSymbolAddress((void**)&Wkh, g_Wkh); cudaGetSymbolAddress((void**)&Wkl, g_Wkl);
    cudaGetSymbolAddress((void**)&Wvh, g_Wvh); cudaGetSymbolAddress((void**)&Wvl, g_Wvl);
    cudaGetSymbolAddress((void**)&qph, g_qph); cudaGetSymbolAddress((void**)&qpl, g_qpl);
    cudaGetSymbolAddress((void**)&kph, g_kph); cudaGetSymbolAddress((void**)&kpl, g_kpl);
    cudaGetSymbolAddress((void**)&vth, g_vth); cudaGetSymbolAddress((void**)&vtl, g_vtl);
    cudaGetSymbolAddress((void**)&ah, g_ah);   cudaGetSymbolAddress((void**)&al, g_al);
    cudaGetSymbolAddress((void**)&att, g_att);

    cudaFuncSetAttribute(gemm_mma<0, 2>, cudaFuncAttributeMaxDynamicSharedMemorySize, SMEMSZ(2));
    cudaFuncSetAttribute(gemm_mma<1, 3>, cudaFuncAttributeMaxDynamicSharedMemorySize, SMEMSZ(3));
    cudaFuncSetAttribute(gemm_mma<2, 3>, cudaFuncAttributeMaxDynamicSharedMemorySize, SMEMSZ(3));

    const float scale = 0.03125f;  // 1024^-0.5  (applied in softmax)
    dim3 blk(256);

    // fp32 -> fp16 hi/lo conversions
    split_kernel<<<SEQ * DIM / 4 / 256, blk>>>(q, qh, ql, SEQ * DIM / 4);
    split_kernel<<<SEQ * DIM / 4 / 256, blk>>>(k, kh, kl, SEQ * DIM / 4);
    split_kernel<<<SEQ * DIM / 4 / 256, blk>>>(v, vh, vl, SEQ * DIM / 4);
    split_kernel<<<DIM * DIM / 4 / 256, blk>>>(Wq, Wqh, Wql, DIM * DIM / 4);
    split_kernel<<<DIM * DIM / 4 / 256, blk>>>(Wk, Wkh, Wkl, DIM * DIM / 4);
    split_kernel<<<DIM * DIM / 4 / 256, blk>>>(Wv, Wvh, Wvl, DIM * DIM / 4);

    // projections (3-term fp16, ~fp32-accurate). NOTE: no scale here.
    dim3 gProj(DIM / 128, SEQ / 128);
    gemm_mma<1, 3><<<gProj, blk, SMEMSZ(3)>>>(qh, ql, Wqh, Wql, bq, nullptr,
                                              qph, qpl, DIM, DIM, 1.0f);
    gemm_mma<1, 3><<<gProj, blk, SMEMSZ(3)>>>(kh, kl, Wkh, Wkl, bk, nullptr,
                                              kph, kpl, DIM, DIM, 1.0f);
    gemm_mma<2, 3><<<gProj, blk, SMEMSZ(3)>>>(vh, vl, Wvh, Wvl, bv, nullptr,
                                              vth, vtl, DIM, DIM, 1.0f);

    // scores = qp @ kp^T  (2-term, fp32 out, unscaled)
    dim3 gScore(SEQ / 128, SEQ / 128);
    gemm_mma<0, 2><<<gScore, blk, SMEMSZ(2)>>>(qph, qpl, kph, nullptr, nullptr,
                                               att, nullptr, nullptr, SEQ, DIM, 1.0f);

    // softmax(scale * scores) + bias -> att hi/lo fp16
    softmax_bias_split<<<SEQ, blk>>>(att, bias, ah, al, scale);

    // out = att @ vp  (2-term, vp accessed as vpT K-major)
    dim3 gOut(DIM / 128, SEQ / 128);
    gemm_mma<0, 2><<<gOut, blk, SMEMSZ(2)>>>(ah, al, vth, nullptr, nullptr,
                                             out, nullptr, nullptr, DIM, SEQ, 1.0f);
}

// round 5
// speedup vs baseline: 2.7366x; 1.0172x over previous
#include <cuda_runtime.h>
#include <cuda_fp16.h>
#include <cstdint>

#define SEQ 4096
#define DIM 1024
typedef __half fp16;

// ---------------- scratch (device globals; allocations forbidden) ----------
__device__ fp16 g_qh[SEQ * DIM], g_ql[SEQ * DIM];
__device__ fp16 g_kh[SEQ * DIM], g_kl[SEQ * DIM];
__device__ fp16 g_vh[SEQ * DIM], g_vl[SEQ * DIM];
__device__ fp16 g_Wq16[DIM * DIM], g_Wk16[DIM * DIM], g_Wv16[DIM * DIM];
__device__ fp16 g_qp16[SEQ * DIM];
__device__ fp16 g_kp16[SEQ * DIM];
__device__ fp16 g_vt16[DIM * SEQ];                    // vp TRANSPOSED [DIM, SEQ]
__device__ float g_att[(size_t)SEQ * SEQ];
__device__ fp16 g_a16[(size_t)SEQ * SEQ];

// ---------------- helpers ---------------------------------------------------
__device__ __forceinline__ uint32_t smem_u32(const void* p) {
    uint32_t a;
    asm("{ .reg .u64 t; cvta.to.shared.u64 t, %1; cvt.u32.u64 %0, t; }"
        : "=r"(a) : "l"(p));
    return a;
}
__device__ __forceinline__ void cpasync16(uint32_t saddr, const void* gptr) {
    asm volatile("cp.async.cg.shared.global [%0], [%1], 16;"
                 :: "r"(saddr), "l"(gptr) : "memory");
}
#define CP_COMMIT() asm volatile("cp.async.commit_group;" ::: "memory")
#define CP_WAIT1()  asm volatile("cp.async.wait_group 1;" ::: "memory")

#define LDSM_X4(r, addr)                                                        \
    asm volatile("ldmatrix.sync.aligned.m8n8.x4.shared.b16 {%0,%1,%2,%3}, [%4];"\
                 : "=r"((r)[0]), "=r"((r)[1]), "=r"((r)[2]), "=r"((r)[3])       \
                 : "r"(addr))
#define LDSM_X2(r, addr)                                                        \
    asm volatile("ldmatrix.sync.aligned.m8n8.x2.shared.b16 {%0,%1}, [%2];"      \
                 : "=r"((r)[0]), "=r"((r)[1]) : "r"(addr))
#define MMA_F16(c, a, b)                                                        \
    asm volatile("mma.sync.aligned.m16n8k16.row.col.f32.f16.f16.f32 "           \
                 "{%0,%1,%2,%3}, {%4,%5,%6,%7}, {%8,%9}, {%0,%1,%2,%3};"        \
                 : "+f"((c)[0]), "+f"((c)[1]), "+f"((c)[2]), "+f"((c)[3])       \
                 : "r"((a)[0]), "r"((a)[1]), "r"((a)[2]), "r"((a)[3]),          \
                   "r"((b)[0]), "r"((b)[1]))

__device__ __forceinline__ void split1(float x, fp16& h, fp16& l) {
    h = __float2half_rn(x);
    l = __float2half_rn(x - __half2float(h));
}

// ---------------- fp32 -> fp16 hi/lo split ----------------------------------
__global__ __launch_bounds__(256)
void split_kernel(const float* __restrict__ x, fp16* __restrict__ h,
                  fp16* __restrict__ l, int n4) {
    int i = blockIdx.x * 256 + threadIdx.x;
    if (i >= n4) return;
    float4 v = reinterpret_cast<const float4*>(x)[i];
    fp16 h0, h1, h2, h3, l0, l1, l2, l3;
    split1(v.x, h0, l0); split1(v.y, h1, l1);
    split1(v.z, h2, l2); split1(v.w, h3, l3);
    __half2* hp = reinterpret_cast<__half2*>(h) + 2 * (size_t)i;
    __half2* lp = reinterpret_cast<__half2*>(l) + 2 * (size_t)i;
    hp[0] = __half2(h0, h1); hp[1] = __half2(h2, h3);
    lp[0] = __half2(l0, l1); lp[1] = __half2(l2, l3);
}

// ---------------- fp32 -> fp16 convert ---------------------------------------
__global__ __launch_bounds__(256)
void cvt_kernel(const float* __restrict__ x, fp16* __restrict__ h, int n4) {
    int i = blockIdx.x * 256 + threadIdx.x;
    if (i >= n4) return;
    float4 v = reinterpret_cast<const float4*>(x)[i];
    __half2* hp = reinterpret_cast<__half2*>(h) + 2 * (size_t)i;
    hp[0] = __half2(__float2half_rn(v.x), __float2half_rn(v.y));
    hp[1] = __half2(__float2half_rn(v.z), __float2half_rn(v.w));
}

// ---------------- split-fp16 mma.sync GEMM ----------------------------------
// C[M,Nn] = A[M,K] @ B[Nn,K]^T  (K-major operands)
//   TERMS==1: acc = Ah·Bh
//   TERMS==2: acc = Ah·Bh + Al·Bh
//   EPI 0: Cf = acc (fp32)
//   EPI 1: (acc+bias)*scale -> fp16 Ch row-major [M,Nn]
//   EPI 2: (acc+bias)       -> fp16 Ch TRANSPOSED [Nn,SEQ]
// 128x128 tile, BK=32, 256 thr (8 warps, 64x32 warp tile), 3-stage cp.async.
#define TSTRIDE 40
#define TILEB (128 * TSTRIDE * 2)            // 10240 B
#define STAGEB(T) (((T) + 1) * TILEB)
#define SMEMSZ(T) (3 * STAGEB(T))

template <int EPI, int TERMS>
__global__ __launch_bounds__(256, 1)
void gemm_mma(const fp16* __restrict__ Ah, const fp16* __restrict__ Al,
              const fp16* __restrict__ Bh,
              const float* __restrict__ bias, float* __restrict__ Cf,
              fp16* __restrict__ Ch,
              int Nn, int K, float scale) {
    extern __shared__ char smem_raw[];
    const uint32_t sbase = smem_u32(smem_raw);
    constexpr int NT = TERMS + 1;              // tiles per stage (A[,Al],B)
    constexpr uint32_t STB = STAGEB(TERMS);
    constexpr int BT = TERMS;                  // index of B tile

    const int tid = threadIdx.x;
    const int wid = tid >> 5;
    const int lane = tid & 31;
    const int mBase = blockIdx.y * 128;
    const int nBase = blockIdx.x * 128;
    const int warp_m = (wid & 1) * 64;
    const int warp_n = (wid >> 1) * 32;

    // global->smem mapping: 2 x 16B per tile per thread
    const int ldRow0 = tid >> 2, ldKc = (tid & 3) * 8;
    const int ldRow1 = ldRow0 + 64;
    const uint32_t sOff0 = ldRow0 * (TSTRIDE * 2) + ldKc * 2;
    const uint32_t sOff1 = ldRow1 * (TSTRIDE * 2) + ldKc * 2;

    const fp16* gT[NT];
    gT[0] = Ah + (size_t)mBase * K;
    if (TERMS == 2) gT[1] = Al + (size_t)mBase * K;
    gT[BT] = Bh + (size_t)nBase * K;

    // ldmatrix per-thread byte offsets within a tile
    const uint32_t aOff = (warp_m + (lane & 15)) * (TSTRIDE * 2) + (lane >> 4) * 16;
    const int bl16 = lane & 15;
    const uint32_t bOff = (warp_n + (bl16 & 7)) * (TSTRIDE * 2) + (bl16 >> 3) * 16;

    float acc[4][4][4];
#pragma unroll
    for (int i = 0; i < 4; i++)
#pragma unroll
        for (int j = 0; j < 4; j++)
#pragma unroll
            for (int p = 0; p < 4; p++) acc[i][j][p] = 0.f;

    const int NIT = K >> 5;

    // prologue: stages 0,1
#pragma unroll
    for (int s = 0; s < 2; s++) {
        const uint32_t nb = sbase + s * STB;
        const int kt = s * 32;
#pragma unroll
        for (int t = 0; t < NT; t++) {
            cpasync16(nb + t * TILEB + sOff0, gT[t] + (size_t)ldRow0 * K + kt + ldKc);
            cpasync16(nb + t * TILEB + sOff1, gT[t] + (size_t)ldRow1 * K + kt + ldKc);
        }
        CP_COMMIT();
    }

    int stage = 0;
    for (int it = 0; it < NIT; it++) {
        CP_WAIT1();
        __syncthreads();

        // issue stage it+2 (overlaps with compute below)
        if (it + 2 < NIT) {
            int ns = stage + 2; if (ns >= 3) ns -= 3;
            const uint32_t nb = sbase + ns * STB;
            const int kt = (it + 2) * 32;
#pragma unroll
            for (int t = 0; t < NT; t++) {
                cpasync16(nb + t * TILEB + sOff0, gT[t] + (size_t)ldRow0 * K + kt + ldKc);
                cpasync16(nb + t * TILEB + sOff1, gT[t] + (size_t)ldRow1 * K + kt + ldKc);
            }
        }
        CP_COMMIT();

        const uint32_t cb = sbase + stage * STB;
#pragma unroll
        for (int ks = 0; ks < 2; ks++) {
            uint32_t af[4][4], alf[4][4], bf[4][2];
            const uint32_t abase = cb + aOff + ks * 32;
            const uint32_t bbase = cb + bOff + ks * 32;
#pragma unroll
            for (int mf = 0; mf < 4; mf++) {
                LDSM_X4(af[mf], abase + 0 * TILEB + mf * (16 * TSTRIDE * 2));
                if (TERMS == 2)
                    LDSM_X4(alf[mf], abase + 1 * TILEB + mf * (16 * TSTRIDE * 2));
            }
#pragma unroll
            for (int nf = 0; nf < 4; nf++)
                LDSM_X2(bf[nf], bbase + BT * TILEB + nf * (8 * TSTRIDE * 2));
#pragma unroll
            for (int mf = 0; mf < 4; mf++)
#pragma unroll
                for (int nf = 0; nf < 4; nf++) MMA_F16(acc[mf][nf], af[mf], bf[nf]);
            if (TERMS == 2) {
#pragma unroll
                for (int mf = 0; mf < 4; mf++)
#pragma unroll
                    for (int nf = 0; nf < 4; nf++) MMA_F16(acc[mf][nf], alf[mf], bf[nf]);
            }
        }
        if (++stage == 3) stage = 0;
    }

    // ------------- epilogue -------------
    if (EPI == 0) {
#pragma unroll
        for (int mf = 0; mf < 4; mf++)
#pragma unroll
            for (int nf = 0; nf < 4; nf++) {
                int row = mBase + warp_m + mf * 16 + (lane >> 2);
                int col = nBase + warp_n + nf * 8 + 2 * (lane & 3);
                float2 v0 = {acc[mf][nf][0], acc[mf][nf][1]};
                float2 v1 = {acc[mf][nf][2], acc[mf][nf][3]};
                *reinterpret_cast<float2*>(&Cf[(size_t)row * Nn + col]) = v0;
                *reinterpret_cast<float2*>(&Cf[(size_t)(row + 8) * Nn + col]) = v1;
            }
    } else if (EPI == 1) {
#pragma unroll
        for (int mf = 0; mf < 4; mf++)
#pragma unroll
            for (int nf = 0; nf < 4; nf++) {
                int row = mBase + warp_m + mf * 16 + (lane >> 2);
                int col = nBase + warp_n + nf * 8 + 2 * (lane & 3);
                float b0 = bias[col], b1 = bias[col + 1];
                float x0 = (acc[mf][nf][0] + b0) * scale;
                float x1 = (acc[mf][nf][1] + b1) * scale;
                float x2 = (acc[mf][nf][2] + b0) * scale;
                float x3 = (acc[mf][nf][3] + b1) * scale;
                *reinterpret_cast<__half2*>(&Ch[(size_t)row * Nn + col]) =
                    __half2(__float2half_rn(x0), __float2half_rn(x1));
                *reinterpret_cast<__half2*>(&Ch[(size_t)(row + 8) * Nn + col]) =
                    __half2(__float2half_rn(x2), __float2half_rn(x3));
            }
    } else {
        // transpose via SMEM then coalesced fp16 store (Ch is [Nn, SEQ])
        float* sb = reinterpret_cast<float*>(smem_raw);
        __syncthreads();
#pragma unroll
        for (int mf = 0; mf < 4; mf++)
#pragma unroll
            for (int nf = 0; nf < 4; nf++) {
                int rl = warp_m + mf * 16 + (lane >> 2);
                int cl = warp_n + nf * 8 + 2 * (lane & 3);
                float b0 = bias[nBase + cl], b1 = bias[nBase + cl + 1];
                sb[cl * 129 + rl] = acc[mf][nf][0] + b0;
                sb[(cl + 1) * 129 + rl] = acc[mf][nf][1] + b1;
                sb[cl * 129 + rl + 8] = acc[mf][nf][2] + b0;
                sb[(cl + 1) * 129 + rl + 8] = acc[mf][nf][3] + b1;
            }
        __syncthreads();
        const int col = tid >> 1;
        const int half = (tid & 1) * 64;
        size_t base = (size_t)(nBase + col) * SEQ + mBase + half;
#pragma unroll
        for (int r = 0; r < 64; r += 2) {
            float x0 = sb[col * 129 + half + r];
            float x1 = sb[col * 129 + half + r + 1];
            *reinterpret_cast<__half2*>(&Ch[base + r]) =
                __half2(__float2half_rn(x0), __float2half_rn(x1));
        }
    }
}

// --------- softmax(scale*scores) + post-softmax bias -> fp16 -----------------
__global__ __launch_bounds__(256)
void softmax_bias_f16(const float* __restrict__ att, const float* __restrict__ bias,
                      fp16* __restrict__ ah, float scale) {
    __shared__ float buf[SEQ];
    __shared__ float red[256];
    const int row = blockIdx.x;
    const int tid = threadIdx.x;
    const float* rp = att + (size_t)row * SEQ;
    const float* bp = bias + (size_t)row * SEQ;

    float lmax = -1e30f;
#pragma unroll
    for (int i = 0; i < 4; i++) {
        int idx = (tid + i * 256) * 4;
        float4 v = *reinterpret_cast<const float4*>(rp + idx);
        v.x *= scale; v.y *= scale; v.z *= scale; v.w *= scale;
        *reinterpret_cast<float4*>(buf + idx) = v;
        lmax = fmaxf(lmax, fmaxf(fmaxf(v.x, v.y), fmaxf(v.z, v.w)));
    }
    red[tid] = lmax;
    __syncthreads();
    for (int s = 128; s > 0; s >>= 1) {
        if (tid < s) red[tid] = fmaxf(red[tid], red[tid + s]);
        __syncthreads();
    }
    float mx = red[0];
    __syncthreads();

    float lsum = 0.f;
#pragma unroll
    for (int i = 0; i < 4; i++) {
        int idx = (tid + i * 256) * 4;
        float4 v = *reinterpret_cast<float4*>(buf + idx);
        v.x = __expf(v.x - mx); v.y = __expf(v.y - mx);
        v.z = __expf(v.z - mx); v.w = __expf(v.w - mx);
        *reinterpret_cast<float4*>(buf + idx) = v;
        lsum += v.x + v.y + v.z + v.w;
    }
    red[tid] = lsum;
    __syncthreads();
    for (int s = 128; s > 0; s >>= 1) {
        if (tid < s) red[tid] += red[tid + s];
        __syncthreads();
    }
    float inv = 1.0f / red[0];

#pragma unroll
    for (int i = 0; i < 4; i++) {
        int idx = (tid + i * 256) * 4;
        float4 v = *reinterpret_cast<float4*>(buf + idx);
        float4 b = *reinterpret_cast<const float4*>(bp + idx);
        __half2 h0 = __half2(__float2half_rn(v.x * inv + b.x),
                             __float2half_rn(v.y * inv + b.y));
        __half2 h1 = __half2(__float2half_rn(v.z * inv + b.z),
                             __float2half_rn(v.w * inv + b.w));
        __half2 hv[2] = {h0, h1};
        *reinterpret_cast<uint2*>(ah + (size_t)row * SEQ + idx) =
            *reinterpret_cast<uint2*>(hv);
    }
}

// ---------------------------------------------------------------------------
extern "C" void kernel_launch(void* const* d_in, const int* in_sizes, int n_in,
                              void* d_out, int out_size) {
    const float* q = (const float*)d_in[0];
    const float* k = (const float*)d_in[1];
    const float* v = (const float*)d_in[2];
    const float* bias = (const float*)d_in[3];
    const float* Wq = (const float*)d_in[4];
    const float* bq = (const float*)d_in[5];
    const float* Wk = (const float*)d_in[6];
    const float* bk = (const float*)d_in[7];
    const float* Wv = (const float*)d_in[8];
    const float* bv = (const float*)d_in[9];
    float* out = (float*)d_out;

    fp16 *qh, *ql, *kh, *kl, *vh, *vl, *Wq16, *Wk16, *Wv16;
    fp16 *qp16, *kp16, *vt16, *a16;
    float* att;
    cudaGetSymbolAddress((void**)&qh, g_qh);     cudaGetSymbolAddress((void**)&ql, g_ql);
    cudaGetSymbolAddress((void**)&kh, g_kh);     cudaGetSymbolAddress((void**)&kl, g_kl);
    cudaGetSymbolAddress((void**)&vh, g_vh);     cudaGetSymbolAddress((void**)&vl, g_vl);
    cudaGetSymbolAddress((void**)&Wq16, g_Wq16); cudaGetSymbolAddress((void**)&Wk16, g_Wk16);
    cudaGetSymbolAddress((void**)&Wv16, g_Wv16);
    cudaGetSymbolAddress((void**)&qp16, g_qp16); cudaGetSymbolAddress((void**)&kp16, g_kp16);
    cudaGetSymbolAddress((void**)&vt16, g_vt16); cudaGetSymbolAddress((void**)&a16, g_a16);
    cudaGetSymbolAddress((void**)&att, g_att);

    cudaFuncSetAttribute(gemm_mma<0, 1>, cudaFuncAttributeMaxDynamicSharedMemorySize, SMEMSZ(1));
    cudaFuncSetAttribute(gemm_mma<1, 2>, cudaFuncAttributeMaxDynamicSharedMemorySize, SMEMSZ(2));
    cudaFuncSetAttribute(gemm_mma<2, 2>, cudaFuncAttributeMaxDynamicSharedMemorySize, SMEMSZ(2));

    const float scale = 0.03125f;  // 1024^-0.5  (applied in softmax)
    dim3 blk(256);

    // input conversions
    split_kernel<<<SEQ * DIM / 4 / 256, blk>>>(q, qh, ql, SEQ * DIM / 4);
    split_kernel<<<SEQ * DIM / 4 / 256, blk>>>(k, kh, kl, SEQ * DIM / 4);
    split_kernel<<<SEQ * DIM / 4 / 256, blk>>>(v, vh, vl, SEQ * DIM / 4);
    cvt_kernel<<<DIM * DIM / 4 / 256, blk>>>(Wq, Wq16, DIM * DIM / 4);
    cvt_kernel<<<DIM * DIM / 4 / 256, blk>>>(Wk, Wk16, DIM * DIM / 4);
    cvt_kernel<<<DIM * DIM / 4 / 256, blk>>>(Wv, Wv16, DIM * DIM / 4);

    // projections (2-term: x split @ W fp16), fp16 outputs
    dim3 gProj(DIM / 128, SEQ / 128);
    gemm_mma<1, 2><<<gProj, blk, SMEMSZ(2)>>>(qh, ql, Wq16, bq, nullptr, qp16,
                                              DIM, DIM, 1.0f);
    gemm_mma<1, 2><<<gProj, blk, SMEMSZ(2)>>>(kh, kl, Wk16, bk, nullptr, kp16,
                                              DIM, DIM, 1.0f);
    gemm_mma<2, 2><<<gProj, blk, SMEMSZ(2)>>>(vh, vl, Wv16, bv, nullptr, vt16,
                                              DIM, DIM, 1.0f);

    // scores = qp @ kp^T  (1-term fp16, fp32 out, unscaled)
    dim3 gScore(SEQ / 128, SEQ / 128);
    gemm_mma<0, 1><<<gScore, blk, SMEMSZ(1)>>>(qp16, nullptr, kp16, nullptr,
                                               att, nullptr, SEQ, DIM, 1.0f);

    // softmax(scale * scores) + bias -> fp16 att
    softmax_bias_f16<<<SEQ, blk>>>(att, bias, a16, scale);

    // out = att @ vp  (1-term fp16, vp accessed as vpT K-major)
    dim3 gOut(DIM / 128, SEQ / 128);
    gemm_mma<0, 1><<<gOut, blk, SMEMSZ(1)>>>(a16, nullptr, vt16, nullptr,
                                             out, nullptr, DIM, SEQ, 1.0f);
}

// round 6
// speedup vs baseline: 4.7944x; 1.7520x over previous
#include <cuda_runtime.h>
#include <cuda_fp16.h>
#include <cstdint>

#define SEQ 4096
#define DIM 1024
typedef __half fp16;

// ---------------- scratch (device globals; allocations forbidden) ----------
__device__ fp16 g_qh[SEQ * DIM], g_ql[SEQ * DIM];
__device__ fp16 g_kh[SEQ * DIM], g_kl[SEQ * DIM];
__device__ fp16 g_vh[SEQ * DIM], g_vl[SEQ * DIM];
__device__ fp16 g_Wq16[DIM * DIM], g_Wk16[DIM * DIM], g_Wv16[DIM * DIM];
__device__ fp16 g_qp16[SEQ * DIM];
__device__ fp16 g_kp16[SEQ * DIM];
__device__ fp16 g_vt16[DIM * SEQ];                    // vp TRANSPOSED [DIM, SEQ]
__device__ float g_att[(size_t)SEQ * SEQ];
__device__ fp16 g_a16[(size_t)SEQ * SEQ];

// ---------------- helpers ---------------------------------------------------
__device__ __forceinline__ uint32_t smem_u32(const void* p) {
    uint32_t a;
    asm("{ .reg .u64 t; cvta.to.shared.u64 t, %1; cvt.u32.u64 %0, t; }"
        : "=r"(a) : "l"(p));
    return a;
}
__device__ __forceinline__ void cpasync16(uint32_t saddr, const void* gptr) {
    asm volatile("cp.async.cg.shared.global [%0], [%1], 16;"
                 :: "r"(saddr), "l"(gptr) : "memory");
}
#define CP_COMMIT() asm volatile("cp.async.commit_group;" ::: "memory")
#define CP_WAIT1()  asm volatile("cp.async.wait_group 1;" ::: "memory")

#define LDSM_X4(r, addr)                                                        \
    asm volatile("ldmatrix.sync.aligned.m8n8.x4.shared.b16 {%0,%1,%2,%3}, [%4];"\
                 : "=r"((r)[0]), "=r"((r)[1]), "=r"((r)[2]), "=r"((r)[3])       \
                 : "r"(addr))
#define LDSM_X2(r, addr)                                                        \
    asm volatile("ldmatrix.sync.aligned.m8n8.x2.shared.b16 {%0,%1}, [%2];"      \
                 : "=r"((r)[0]), "=r"((r)[1]) : "r"(addr))
#define MMA_F16(c, a, b)                                                        \
    asm volatile("mma.sync.aligned.m16n8k16.row.col.f32.f16.f16.f32 "           \
                 "{%0,%1,%2,%3}, {%4,%5,%6,%7}, {%8,%9}, {%0,%1,%2,%3};"        \
                 : "+f"((c)[0]), "+f"((c)[1]), "+f"((c)[2]), "+f"((c)[3])       \
                 : "r"((a)[0]), "r"((a)[1]), "r"((a)[2]), "r"((a)[3]),          \
                   "r"((b)[0]), "r"((b)[1]))

__device__ __forceinline__ void split1(float x, fp16& h, fp16& l) {
    h = __float2half_rn(x);
    l = __float2half_rn(x - __half2float(h));
}

// ---------------- fp32 -> fp16 hi/lo split ----------------------------------
__global__ __launch_bounds__(256)
void split_kernel(const float* __restrict__ x, fp16* __restrict__ h,
                  fp16* __restrict__ l, int n4) {
    int i = blockIdx.x * 256 + threadIdx.x;
    if (i >= n4) return;
    float4 v = reinterpret_cast<const float4*>(x)[i];
    fp16 h0, h1, h2, h3, l0, l1, l2, l3;
    split1(v.x, h0, l0); split1(v.y, h1, l1);
    split1(v.z, h2, l2); split1(v.w, h3, l3);
    __half2* hp = reinterpret_cast<__half2*>(h) + 2 * (size_t)i;
    __half2* lp = reinterpret_cast<__half2*>(l) + 2 * (size_t)i;
    hp[0] = __half2(h0, h1); hp[1] = __half2(h2, h3);
    lp[0] = __half2(l0, l1); lp[1] = __half2(l2, l3);
}

// ---------------- fp32 -> fp16 convert ---------------------------------------
__global__ __launch_bounds__(256)
void cvt_kernel(const float* __restrict__ x, fp16* __restrict__ h, int n4) {
    int i = blockIdx.x * 256 + threadIdx.x;
    if (i >= n4) return;
    float4 v = reinterpret_cast<const float4*>(x)[i];
    __half2* hp = reinterpret_cast<__half2*>(h) + 2 * (size_t)i;
    hp[0] = __half2(__float2half_rn(v.x), __float2half_rn(v.y));
    hp[1] = __half2(__float2half_rn(v.z), __float2half_rn(v.w));
}

// ---------------- split-fp16 mma.sync GEMM, BK=64 ---------------------------
// C[M,Nn] = A[M,K] @ B[Nn,K]^T  (K-major operands)
//   TERMS==1: acc = Ah·Bh            (min 2 blocks/SM)
//   TERMS==2: acc = Ah·Bh + Al·Bh
//   EPI 0: Cf = acc (fp32)
//   EPI 1: (acc+bias)*scale -> fp16 Ch row-major [M,Nn]
//   EPI 2: (acc+bias)       -> fp16 Ch TRANSPOSED [Nn,SEQ]
// 128x128 tile, BK=64, 256 thr (8 warps, 64x32 warp tile), 3-stage cp.async.
#define TSTRIDE 72                            // 64 halves + 8 pad (144 B rows)
#define TILEB (128 * TSTRIDE * 2)             // 18432 B
#define STAGEB(T) (((T) + 1) * TILEB)
#define SMEMSZ(T) (3 * STAGEB(T))             // T=1: 110592, T=2: 165888

template <int EPI, int TERMS>
__global__ __launch_bounds__(256, (TERMS == 1 ? 2 : 1))
void gemm_mma(const fp16* __restrict__ Ah, const fp16* __restrict__ Al,
              const fp16* __restrict__ Bh,
              const float* __restrict__ bias, float* __restrict__ Cf,
              fp16* __restrict__ Ch,
              int Nn, int K, float scale) {
    extern __shared__ char smem_raw[];
    const uint32_t sbase = smem_u32(smem_raw);
    constexpr int NT = TERMS + 1;              // tiles per stage (A[,Al],B)
    constexpr uint32_t STB = STAGEB(TERMS);
    constexpr int BT = TERMS;                  // index of B tile

    const int tid = threadIdx.x;
    const int wid = tid >> 5;
    const int lane = tid & 31;
    const int mBase = blockIdx.y * 128;
    const int nBase = blockIdx.x * 128;
    const int warp_m = (wid & 1) * 64;
    const int warp_n = (wid >> 1) * 32;

    // global->smem mapping: 4 x 16B chunks per tile per thread (128r x 64h)
    const int ldRow = tid >> 3;               // 0..31 (+32 per j)
    const int ldKc = (tid & 7) * 8;           // halves
    const uint32_t sOff = ldRow * (TSTRIDE * 2) + ldKc * 2;

    const fp16* gT[NT];
    gT[0] = Ah + (size_t)mBase * K;
    if (TERMS == 2) gT[1] = Al + (size_t)mBase * K;
    gT[BT] = Bh + (size_t)nBase * K;

    // ldmatrix per-thread byte offsets within a tile
    const uint32_t aOff = (warp_m + (lane & 15)) * (TSTRIDE * 2) + (lane >> 4) * 16;
    const int bl16 = lane & 15;
    const uint32_t bOff = (warp_n + (bl16 & 7)) * (TSTRIDE * 2) + (bl16 >> 3) * 16;

    float acc[4][4][4];
#pragma unroll
    for (int i = 0; i < 4; i++)
#pragma unroll
        for (int j = 0; j < 4; j++)
#pragma unroll
            for (int p = 0; p < 4; p++) acc[i][j][p] = 0.f;

    const int NIT = K >> 6;                   // K / 64

    // prologue: stages 0,1
#pragma unroll
    for (int s = 0; s < 2; s++) {
        const uint32_t nb = sbase + s * STB;
        const int kt = s * 64;
#pragma unroll
        for (int t = 0; t < NT; t++)
#pragma unroll
            for (int j = 0; j < 4; j++)
                cpasync16(nb + t * TILEB + sOff + j * 32 * (TSTRIDE * 2),
                          gT[t] + (size_t)(ldRow + j * 32) * K + kt + ldKc);
        CP_COMMIT();
    }

    int stage = 0;
    for (int it = 0; it < NIT; it++) {
        CP_WAIT1();
        __syncthreads();

        // issue stage it+2 (overlaps with compute below)
        if (it + 2 < NIT) {
            int ns = stage + 2; if (ns >= 3) ns -= 3;
            const uint32_t nb = sbase + ns * STB;
            const int kt = (it + 2) * 64;
#pragma unroll
            for (int t = 0; t < NT; t++)
#pragma unroll
                for (int j = 0; j < 4; j++)
                    cpasync16(nb + t * TILEB + sOff + j * 32 * (TSTRIDE * 2),
                              gT[t] + (size_t)(ldRow + j * 32) * K + kt + ldKc);
        }
        CP_COMMIT();

        const uint32_t cb = sbase + stage * STB;
#pragma unroll
        for (int ks = 0; ks < 4; ks++) {
            uint32_t af[4][4], alf[4][4], bf[4][2];
            const uint32_t abase = cb + aOff + ks * 32;
            const uint32_t bbase = cb + bOff + ks * 32;
#pragma unroll
            for (int mf = 0; mf < 4; mf++) {
                LDSM_X4(af[mf], abase + 0 * TILEB + mf * (16 * TSTRIDE * 2));
                if (TERMS == 2)
                    LDSM_X4(alf[mf], abase + 1 * TILEB + mf * (16 * TSTRIDE * 2));
            }
#pragma unroll
            for (int nf = 0; nf < 4; nf++)
                LDSM_X2(bf[nf], bbase + BT * TILEB + nf * (8 * TSTRIDE * 2));
#pragma unroll
            for (int mf = 0; mf < 4; mf++)
#pragma unroll
                for (int nf = 0; nf < 4; nf++) MMA_F16(acc[mf][nf], af[mf], bf[nf]);
            if (TERMS == 2) {
#pragma unroll
                for (int mf = 0; mf < 4; mf++)
#pragma unroll
                    for (int nf = 0; nf < 4; nf++) MMA_F16(acc[mf][nf], alf[mf], bf[nf]);
            }
        }
        if (++stage == 3) stage = 0;
    }

    // ------------- epilogue -------------
    if (EPI == 0) {
#pragma unroll
        for (int mf = 0; mf < 4; mf++)
#pragma unroll
            for (int nf = 0; nf < 4; nf++) {
                int row = mBase + warp_m + mf * 16 + (lane >> 2);
                int col = nBase + warp_n + nf * 8 + 2 * (lane & 3);
                float2 v0 = {acc[mf][nf][0], acc[mf][nf][1]};
                float2 v1 = {acc[mf][nf][2], acc[mf][nf][3]};
                *reinterpret_cast<float2*>(&Cf[(size_t)row * Nn + col]) = v0;
                *reinterpret_cast<float2*>(&Cf[(size_t)(row + 8) * Nn + col]) = v1;
            }
    } else if (EPI == 1) {
#pragma unroll
        for (int mf = 0; mf < 4; mf++)
#pragma unroll
            for (int nf = 0; nf < 4; nf++) {
                int row = mBase + warp_m + mf * 16 + (lane >> 2);
                int col = nBase + warp_n + nf * 8 + 2 * (lane & 3);
                float b0 = bias[col], b1 = bias[col + 1];
                float x0 = (acc[mf][nf][0] + b0) * scale;
                float x1 = (acc[mf][nf][1] + b1) * scale;
                float x2 = (acc[mf][nf][2] + b0) * scale;
                float x3 = (acc[mf][nf][3] + b1) * scale;
                *reinterpret_cast<__half2*>(&Ch[(size_t)row * Nn + col]) =
                    __half2(__float2half_rn(x0), __float2half_rn(x1));
                *reinterpret_cast<__half2*>(&Ch[(size_t)(row + 8) * Nn + col]) =
                    __half2(__float2half_rn(x2), __float2half_rn(x3));
            }
    } else {
        // transpose via SMEM then coalesced fp16 store (Ch is [Nn, SEQ])
        float* sb = reinterpret_cast<float*>(smem_raw);
        __syncthreads();
#pragma unroll
        for (int mf = 0; mf < 4; mf++)
#pragma unroll
            for (int nf = 0; nf < 4; nf++) {
                int rl = warp_m + mf * 16 + (lane >> 2);
                int cl = warp_n + nf * 8 + 2 * (lane & 3);
                float b0 = bias[nBase + cl], b1 = bias[nBase + cl + 1];
                sb[cl * 129 + rl] = acc[mf][nf][0] + b0;
                sb[(cl + 1) * 129 + rl] = acc[mf][nf][1] + b1;
                sb[cl * 129 + rl + 8] = acc[mf][nf][2] + b0;
                sb[(cl + 1) * 129 + rl + 8] = acc[mf][nf][3] + b1;
            }
        __syncthreads();
        const int col = tid >> 1;
        const int half = (tid & 1) * 64;
        size_t base = (size_t)(nBase + col) * SEQ + mBase + half;
#pragma unroll
        for (int r = 0; r < 64; r += 2) {
            float x0 = sb[col * 129 + half + r];
            float x1 = sb[col * 129 + half + r + 1];
            *reinterpret_cast<__half2*>(&Ch[base + r]) =
                __half2(__float2half_rn(x0), __float2half_rn(x1));
        }
    }
}

// --------- softmax(scale*scores) + post-softmax bias -> fp16 -----------------
__global__ __launch_bounds__(256)
void softmax_bias_f16(const float* __restrict__ att, const float* __restrict__ bias,
                      fp16* __restrict__ ah, float scale) {
    __shared__ float buf[SEQ];
    __shared__ float red[256];
    const int row = blockIdx.x;
    const int tid = threadIdx.x;
    const float* rp = att + (size_t)row * SEQ;
    const float* bp = bias + (size_t)row * SEQ;

    float lmax = -1e30f;
#pragma unroll
    for (int i = 0; i < 4; i++) {
        int idx = (tid + i * 256) * 4;
        float4 v = *reinterpret_cast<const float4*>(rp + idx);
        v.x *= scale; v.y *= scale; v.z *= scale; v.w *= scale;
        *reinterpret_cast<float4*>(buf + idx) = v;
        lmax = fmaxf(lmax, fmaxf(fmaxf(v.x, v.y), fmaxf(v.z, v.w)));
    }
    red[tid] = lmax;
    __syncthreads();
    for (int s = 128; s > 0; s >>= 1) {
        if (tid < s) red[tid] = fmaxf(red[tid], red[tid + s]);
        __syncthreads();
    }
    float mx = red[0];
    __syncthreads();

    float lsum = 0.f;
#pragma unroll
    for (int i = 0; i < 4; i++) {
        int idx = (tid + i * 256) * 4;
        float4 v = *reinterpret_cast<float4*>(buf + idx);
        v.x = __expf(v.x - mx); v.y = __expf(v.y - mx);
        v.z = __expf(v.z - mx); v.w = __expf(v.w - mx);
        *reinterpret_cast<float4*>(buf + idx) = v;
        lsum += v.x + v.y + v.z + v.w;
    }
    red[tid] = lsum;
    __syncthreads();
    for (int s = 128; s > 0; s >>= 1) {
        if (tid < s) red[tid] += red[tid + s];
        __syncthreads();
    }
    float inv = 1.0f / red[0];

#pragma unroll
    for (int i = 0; i < 4; i++) {
        int idx = (tid + i * 256) * 4;
        float4 v = *reinterpret_cast<float4*>(buf + idx);
        float4 b = *reinterpret_cast<const float4*>(bp + idx);
        __half2 h0 = __half2(__float2half_rn(v.x * inv + b.x),
                             __float2half_rn(v.y * inv + b.y));
        __half2 h1 = __half2(__float2half_rn(v.z * inv + b.z),
                             __float2half_rn(v.w * inv + b.w));
        __half2 hv[2] = {h0, h1};
        *reinterpret_cast<uint2*>(ah + (size_t)row * SEQ + idx) =
            *reinterpret_cast<uint2*>(hv);
    }
}

// ---------------------------------------------------------------------------
extern "C" void kernel_launch(void* const* d_in, const int* in_sizes, int n_in,
                              void* d_out, int out_size) {
    const float* q = (const float*)d_in[0];
    const float* k = (const float*)d_in[1];
    const float* v = (const float*)d_in[2];
    const float* bias = (const float*)d_in[3];
    const float* Wq = (const float*)d_in[4];
    const float* bq = (const float*)d_in[5];
    const float* Wk = (const float*)d_in[6];
    const float* bk = (const float*)d_in[7];
    const float* Wv = (const float*)d_in[8];
    const float* bv = (const float*)d_in[9];
    float* out = (float*)d_out;

    fp16 *qh, *ql, *kh, *kl, *vh, *vl, *Wq16, *Wk16, *Wv16;
    fp16 *qp16, *kp16, *vt16, *a16;
    float* att;
    cudaGetSymbolAddress((void**)&qh, g_qh);     cudaGetSymbolAddress((void**)&ql, g_ql);
    cudaGetSymbolAddress((void**)&kh, g_kh);     cudaGetSymbolAddress((void**)&kl, g_kl);
    cudaGetSymbolAddress((void**)&vh, g_vh);     cudaGetSymbolAddress((void**)&vl, g_vl);
    cudaGetSymbolAddress((void**)&Wq16, g_Wq16); cudaGetSymbolAddress((void**)&Wk16, g_Wk16);
    cudaGetSymbolAddress((void**)&Wv16, g_Wv16);
    cudaGetSymbolAddress((void**)&qp16, g_qp16); cudaGetSymbolAddress((void**)&kp16, g_kp16);
    cudaGetSymbolAddress((void**)&vt16, g_vt16); cudaGetSymbolAddress((void**)&a16, g_a16);
    cudaGetSymbolAddress((void**)&att, g_att);

    cudaFuncSetAttribute(gemm_mma<0, 1>, cudaFuncAttributeMaxDynamicSharedMemorySize, SMEMSZ(1));
    cudaFuncSetAttribute(gemm_mma<1, 2>, cudaFuncAttributeMaxDynamicSharedMemorySize, SMEMSZ(2));
    cudaFuncSetAttribute(gemm_mma<2, 2>, cudaFuncAttributeMaxDynamicSharedMemorySize, SMEMSZ(2));

    const float scale = 0.03125f;  // 1024^-0.5  (applied in softmax)
    dim3 blk(256);

    // input conversions
    split_kernel<<<SEQ * DIM / 4 / 256, blk>>>(q, qh, ql, SEQ * DIM / 4);
    split_kernel<<<SEQ * DIM / 4 / 256, blk>>>(k, kh, kl, SEQ * DIM / 4);
    split_kernel<<<SEQ * DIM / 4 / 256, blk>>>(v, vh, vl, SEQ * DIM / 4);
    cvt_kernel<<<DIM * DIM / 4 / 256, blk>>>(Wq, Wq16, DIM * DIM / 4);
    cvt_kernel<<<DIM * DIM / 4 / 256, blk>>>(Wk, Wk16, DIM * DIM / 4);
    cvt_kernel<<<DIM * DIM / 4 / 256, blk>>>(Wv, Wv16, DIM * DIM / 4);

    // projections (2-term: x split @ W fp16), fp16 outputs
    dim3 gProj(DIM / 128, SEQ / 128);
    gemm_mma<1, 2><<<gProj, blk, SMEMSZ(2)>>>(qh, ql, Wq16, bq, nullptr, qp16,
                                              DIM, DIM, 1.0f);
    gemm_mma<1, 2><<<gProj, blk, SMEMSZ(2)>>>(kh, kl, Wk16, bk, nullptr, kp16,
                                              DIM, DIM, 1.0f);
    gemm_mma<2, 2><<<gProj, blk, SMEMSZ(2)>>>(vh, vl, Wv16, bv, nullptr, vt16,
                                              DIM, DIM, 1.0f);

    // scores = qp @ kp^T  (1-term fp16, fp32 out, unscaled)
    dim3 gScore(SEQ / 128, SEQ / 128);
    gemm_mma<0, 1><<<gScore, blk, SMEMSZ(1)>>>(qp16, nullptr, kp16, nullptr,
                                               att, nullptr, SEQ, DIM, 1.0f);

    // softmax(scale * scores) + bias -> fp16 att
    softmax_bias_f16<<<SEQ, blk>>>(att, bias, a16, scale);

    // out = att @ vp  (1-term fp16, vp accessed as vpT K-major)
    dim3 gOut(DIM / 128, SEQ / 128);
    gemm_mma<0, 1><<<gOut, blk, SMEMSZ(1)>>>(a16, nullptr, vt16, nullptr,
                                             out, nullptr, DIM, SEQ, 1.0f);
}

// round 7
// speedup vs baseline: 5.9987x; 1.2512x over previous
#include <cuda_runtime.h>
#include <cuda_fp16.h>
#include <cstdint>

#define SEQ 4096
#define DIM 1024
typedef __half fp16;

// ---------------- scratch (device globals; allocations forbidden) ----------
__device__ fp16 g_q16[SEQ * DIM], g_k16[SEQ * DIM], g_v16[SEQ * DIM];
__device__ fp16 g_Wq16[DIM * DIM], g_Wk16[DIM * DIM], g_Wv16[DIM * DIM];
__device__ fp16 g_qp16[SEQ * DIM];
__device__ fp16 g_kp16[SEQ * DIM];
__device__ fp16 g_vt16[DIM * SEQ];                    // vp TRANSPOSED [DIM, SEQ]
__device__ float g_att[(size_t)SEQ * SEQ];
__device__ fp16 g_a16[(size_t)SEQ * SEQ];

// ---------------- helpers ---------------------------------------------------
__device__ __forceinline__ uint32_t smem_u32(const void* p) {
    uint32_t a;
    asm("{ .reg .u64 t; cvta.to.shared.u64 t, %1; cvt.u32.u64 %0, t; }"
        : "=r"(a) : "l"(p));
    return a;
}
__device__ __forceinline__ void cpasync16(uint32_t saddr, const void* gptr) {
    asm volatile("cp.async.cg.shared.global [%0], [%1], 16;"
                 :: "r"(saddr), "l"(gptr) : "memory");
}
#define CP_COMMIT() asm volatile("cp.async.commit_group;" ::: "memory")
#define CP_WAIT1()  asm volatile("cp.async.wait_group 1;" ::: "memory")

#define LDSM_X4(r, addr)                                                        \
    asm volatile("ldmatrix.sync.aligned.m8n8.x4.shared.b16 {%0,%1,%2,%3}, [%4];"\
                 : "=r"((r)[0]), "=r"((r)[1]), "=r"((r)[2]), "=r"((r)[3])       \
                 : "r"(addr))
#define LDSM_X2(r, addr)                                                        \
    asm volatile("ldmatrix.sync.aligned.m8n8.x2.shared.b16 {%0,%1}, [%2];"      \
                 : "=r"((r)[0]), "=r"((r)[1]) : "r"(addr))
#define MMA_F16(c, a, b)                                                        \
    asm volatile("mma.sync.aligned.m16n8k16.row.col.f32.f16.f16.f32 "           \
                 "{%0,%1,%2,%3}, {%4,%5,%6,%7}, {%8,%9}, {%0,%1,%2,%3};"        \
                 : "+f"((c)[0]), "+f"((c)[1]), "+f"((c)[2]), "+f"((c)[3])       \
                 : "r"((a)[0]), "r"((a)[1]), "r"((a)[2]), "r"((a)[3]),          \
                   "r"((b)[0]), "r"((b)[1]))

// ---------------- batched fp32 -> fp16 convert (3 tensors per launch) --------
__global__ __launch_bounds__(256)
void cvt3_kernel(const float* __restrict__ x0, const float* __restrict__ x1,
                 const float* __restrict__ x2, fp16* __restrict__ y0,
                 fp16* __restrict__ y1, fp16* __restrict__ y2, int n4) {
    int i = blockIdx.x * 256 + threadIdx.x;
    if (i >= n4) return;
    const float* x = (blockIdx.y == 0) ? x0 : (blockIdx.y == 1) ? x1 : x2;
    fp16* y = (blockIdx.y == 0) ? y0 : (blockIdx.y == 1) ? y1 : y2;
    float4 v = reinterpret_cast<const float4*>(x)[i];
    __half2* hp = reinterpret_cast<__half2*>(y) + 2 * (size_t)i;
    hp[0] = __half2(__float2half_rn(v.x), __float2half_rn(v.y));
    hp[1] = __half2(__float2half_rn(v.z), __float2half_rn(v.w));
}

// ---------------- fp16 mma.sync GEMM, BK=64, 1 term -------------------------
// C[M,Nn] = A[M,K] @ B[Nn,K]^T  (K-major fp16 operands, fp32 accum)
//   EPI 0: Cf = acc (fp32)
//   EPI 1: (acc+bias)*scale -> fp16 Ch row-major [M,Nn]
//   EPI 2: (acc+bias)       -> fp16 Ch TRANSPOSED [Nn,SEQ]
// 128x128 tile, BK=64, 256 thr (8 warps, 64x32 warp tile), 3-stage cp.async,
// 2 CTAs/SM.
#define TSTRIDE 72                            // 64 halves + 8 pad (144 B rows)
#define TILEB (128 * TSTRIDE * 2)             // 18432 B
#define STAGEB (2 * TILEB)                    // A, B
#define SMEM_SZ (3 * STAGEB)                  // 110592 B

template <int EPI>
__global__ __launch_bounds__(256, 2)
void gemm_mma(const fp16* __restrict__ A, const fp16* __restrict__ B,
              const float* __restrict__ bias, float* __restrict__ Cf,
              fp16* __restrict__ Ch,
              int Nn, int K, float scale) {
    extern __shared__ char smem_raw[];
    const uint32_t sbase = smem_u32(smem_raw);

    const int tid = threadIdx.x;
    const int wid = tid >> 5;
    const int lane = tid & 31;
    const int mBase = blockIdx.y * 128;
    const int nBase = blockIdx.x * 128;
    const int warp_m = (wid & 1) * 64;
    const int warp_n = (wid >> 1) * 32;

    // global->smem mapping: 4 x 16B chunks per tile per thread (128r x 64h)
    const int ldRow = tid >> 3;               // 0..31 (+32 per j)
    const int ldKc = (tid & 7) * 8;           // halves
    const uint32_t sOff = ldRow * (TSTRIDE * 2) + ldKc * 2;

    const fp16* gA = A + (size_t)mBase * K;
    const fp16* gB = B + (size_t)nBase * K;

    // ldmatrix per-thread byte offsets within a tile
    const uint32_t aOff = (warp_m + (lane & 15)) * (TSTRIDE * 2) + (lane >> 4) * 16;
    const int bl16 = lane & 15;
    const uint32_t bOff = (warp_n + (bl16 & 7)) * (TSTRIDE * 2) + (bl16 >> 3) * 16;

    float acc[4][4][4];
#pragma unroll
    for (int i = 0; i < 4; i++)
#pragma unroll
        for (int j = 0; j < 4; j++)
#pragma unroll
            for (int p = 0; p < 4; p++) acc[i][j][p] = 0.f;

    const int NIT = K >> 6;                   // K / 64

    // prologue: stages 0,1
#pragma unroll
    for (int s = 0; s < 2; s++) {
        const uint32_t nb = sbase + s * STAGEB;
        const int kt = s * 64;
#pragma unroll
        for (int j = 0; j < 4; j++) {
            cpasync16(nb + sOff + j * 32 * (TSTRIDE * 2),
                      gA + (size_t)(ldRow + j * 32) * K + kt + ldKc);
            cpasync16(nb + TILEB + sOff + j * 32 * (TSTRIDE * 2),
                      gB + (size_t)(ldRow + j * 32) * K + kt + ldKc);
        }
        CP_COMMIT();
    }

    int stage = 0;
    for (int it = 0; it < NIT; it++) {
        CP_WAIT1();
        __syncthreads();

        // issue stage it+2 (overlaps with compute below)
        if (it + 2 < NIT) {
            int ns = stage + 2; if (ns >= 3) ns -= 3;
            const uint32_t nb = sbase + ns * STAGEB;
            const int kt = (it + 2) * 64;
#pragma unroll
            for (int j = 0; j < 4; j++) {
                cpasync16(nb + sOff + j * 32 * (TSTRIDE * 2),
                          gA + (size_t)(ldRow + j * 32) * K + kt + ldKc);
                cpasync16(nb + TILEB + sOff + j * 32 * (TSTRIDE * 2),
                          gB + (size_t)(ldRow + j * 32) * K + kt + ldKc);
            }
        }
        CP_COMMIT();

        const uint32_t cb = sbase + stage * STAGEB;
#pragma unroll
        for (int ks = 0; ks < 4; ks++) {
            uint32_t af[4][4], bf[4][2];
            const uint32_t abase = cb + aOff + ks * 32;
            const uint32_t bbase = cb + TILEB + bOff + ks * 32;
#pragma unroll
            for (int mf = 0; mf < 4; mf++)
                LDSM_X4(af[mf], abase + mf * (16 * TSTRIDE * 2));
#pragma unroll
            for (int nf = 0; nf < 4; nf++)
                LDSM_X2(bf[nf], bbase + nf * (8 * TSTRIDE * 2));
#pragma unroll
            for (int mf = 0; mf < 4; mf++)
#pragma unroll
                for (int nf = 0; nf < 4; nf++) MMA_F16(acc[mf][nf], af[mf], bf[nf]);
        }
        if (++stage == 3) stage = 0;
    }

    // ------------- epilogue -------------
    if (EPI == 0) {
#pragma unroll
        for (int mf = 0; mf < 4; mf++)
#pragma unroll
            for (int nf = 0; nf < 4; nf++) {
                int row = mBase + warp_m + mf * 16 + (lane >> 2);
                int col = nBase + warp_n + nf * 8 + 2 * (lane & 3);
                float2 v0 = {acc[mf][nf][0], acc[mf][nf][1]};
                float2 v1 = {acc[mf][nf][2], acc[mf][nf][3]};
                *reinterpret_cast<float2*>(&Cf[(size_t)row * Nn + col]) = v0;
                *reinterpret_cast<float2*>(&Cf[(size_t)(row + 8) * Nn + col]) = v1;
            }
    } else if (EPI == 1) {
#pragma unroll
        for (int mf = 0; mf < 4; mf++)
#pragma unroll
            for (int nf = 0; nf < 4; nf++) {
                int row = mBase + warp_m + mf * 16 + (lane >> 2);
                int col = nBase + warp_n + nf * 8 + 2 * (lane & 3);
                float b0 = bias[col], b1 = bias[col + 1];
                float x0 = (acc[mf][nf][0] + b0) * scale;
                float x1 = (acc[mf][nf][1] + b1) * scale;
                float x2 = (acc[mf][nf][2] + b0) * scale;
                float x3 = (acc[mf][nf][3] + b1) * scale;
                *reinterpret_cast<__half2*>(&Ch[(size_t)row * Nn + col]) =
                    __half2(__float2half_rn(x0), __float2half_rn(x1));
                *reinterpret_cast<__half2*>(&Ch[(size_t)(row + 8) * Nn + col]) =
                    __half2(__float2half_rn(x2), __float2half_rn(x3));
            }
    } else {
        // transpose via SMEM then coalesced fp16 store (Ch is [Nn, SEQ])
        float* sb = reinterpret_cast<float*>(smem_raw);
        __syncthreads();
#pragma unroll
        for (int mf = 0; mf < 4; mf++)
#pragma unroll
            for (int nf = 0; nf < 4; nf++) {
                int rl = warp_m + mf * 16 + (lane >> 2);
                int cl = warp_n + nf * 8 + 2 * (lane & 3);
                float b0 = bias[nBase + cl], b1 = bias[nBase + cl + 1];
                sb[cl * 129 + rl] = acc[mf][nf][0] + b0;
                sb[(cl + 1) * 129 + rl] = acc[mf][nf][1] + b1;
                sb[cl * 129 + rl + 8] = acc[mf][nf][2] + b0;
                sb[(cl + 1) * 129 + rl + 8] = acc[mf][nf][3] + b1;
            }
        __syncthreads();
        const int col = tid >> 1;
        const int half = (tid & 1) * 64;
        size_t base = (size_t)(nBase + col) * SEQ + mBase + half;
#pragma unroll
        for (int r = 0; r < 64; r += 2) {
            float x0 = sb[col * 129 + half + r];
            float x1 = sb[col * 129 + half + r + 1];
            *reinterpret_cast<__half2*>(&Ch[base + r]) =
                __half2(__float2half_rn(x0), __float2half_rn(x1));
        }
    }
}

// --------- softmax(scale*scores) + post-softmax bias -> fp16 -----------------
__global__ __launch_bounds__(256)
void softmax_bias_f16(const float* __restrict__ att, const float* __restrict__ bias,
                      fp16* __restrict__ ah, float scale) {
    __shared__ float buf[SEQ];
    __shared__ float red[256];
    const int row = blockIdx.x;
    const int tid = threadIdx.x;
    const float* rp = att + (size_t)row * SEQ;
    const float* bp = bias + (size_t)row * SEQ;

    float lmax = -1e30f;
#pragma unroll
    for (int i = 0; i < 4; i++) {
        int idx = (tid + i * 256) * 4;
        float4 v = *reinterpret_cast<const float4*>(rp + idx);
        v.x *= scale; v.y *= scale; v.z *= scale; v.w *= scale;
        *reinterpret_cast<float4*>(buf + idx) = v;
        lmax = fmaxf(lmax, fmaxf(fmaxf(v.x, v.y), fmaxf(v.z, v.w)));
    }
    red[tid] = lmax;
    __syncthreads();
    for (int s = 128; s > 0; s >>= 1) {
        if (tid < s) red[tid] = fmaxf(red[tid], red[tid + s]);
        __syncthreads();
    }
    float mx = red[0];
    __syncthreads();

    float lsum = 0.f;
#pragma unroll
    for (int i = 0; i < 4; i++) {
        int idx = (tid + i * 256) * 4;
        float4 v = *reinterpret_cast<float4*>(buf + idx);
        v.x = __expf(v.x - mx); v.y = __expf(v.y - mx);
        v.z = __expf(v.z - mx); v.w = __expf(v.w - mx);
        *reinterpret_cast<float4*>(buf + idx) = v;
        lsum += v.x + v.y + v.z + v.w;
    }
    red[tid] = lsum;
    __syncthreads();
    for (int s = 128; s > 0; s >>= 1) {
        if (tid < s) red[tid] += red[tid + s];
        __syncthreads();
    }
    float inv = 1.0f / red[0];

#pragma unroll
    for (int i = 0; i < 4; i++) {
        int idx = (tid + i * 256) * 4;
        float4 v = *reinterpret_cast<float4*>(buf + idx);
        float4 b = *reinterpret_cast<const float4*>(bp + idx);
        __half2 h0 = __half2(__float2half_rn(v.x * inv + b.x),
                             __float2half_rn(v.y * inv + b.y));
        __half2 h1 = __half2(__float2half_rn(v.z * inv + b.z),
                             __float2half_rn(v.w * inv + b.w));
        __half2 hv[2] = {h0, h1};
        *reinterpret_cast<uint2*>(ah + (size_t)row * SEQ + idx) =
            *reinterpret_cast<uint2*>(hv);
    }
}

// ---------------------------------------------------------------------------
extern "C" void kernel_launch(void* const* d_in, const int* in_sizes, int n_in,
                              void* d_out, int out_size) {
    const float* q = (const float*)d_in[0];
    const float* k = (const float*)d_in[1];
    const float* v = (const float*)d_in[2];
    const float* bias = (const float*)d_in[3];
    const float* Wq = (const float*)d_in[4];
    const float* bq = (const float*)d_in[5];
    const float* Wk = (const float*)d_in[6];
    const float* bk = (const float*)d_in[7];
    const float* Wv = (const float*)d_in[8];
    const float* bv = (const float*)d_in[9];
    float* out = (float*)d_out;

    fp16 *q16, *k16, *v16, *Wq16, *Wk16, *Wv16;
    fp16 *qp16, *kp16, *vt16, *a16;
    float* att;
    cudaGetSymbolAddress((void**)&q16, g_q16);   cudaGetSymbolAddress((void**)&k16, g_k16);
    cudaGetSymbolAddress((void**)&v16, g_v16);
    cudaGetSymbolAddress((void**)&Wq16, g_Wq16); cudaGetSymbolAddress((void**)&Wk16, g_Wk16);
    cudaGetSymbolAddress((void**)&Wv16, g_Wv16);
    cudaGetSymbolAddress((void**)&qp16, g_qp16); cudaGetSymbolAddress((void**)&kp16, g_kp16);
    cudaGetSymbolAddress((void**)&vt16, g_vt16); cudaGetSymbolAddress((void**)&a16, g_a16);
    cudaGetSymbolAddress((void**)&att, g_att);

    cudaFuncSetAttribute(gemm_mma<0>, cudaFuncAttributeMaxDynamicSharedMemorySize, SMEM_SZ);
    cudaFuncSetAttribute(gemm_mma<1>, cudaFuncAttributeMaxDynamicSharedMemorySize, SMEM_SZ);
    cudaFuncSetAttribute(gemm_mma<2>, cudaFuncAttributeMaxDynamicSharedMemorySize, SMEM_SZ);

    const float scale = 0.03125f;  // 1024^-0.5  (applied in softmax)
    dim3 blk(256);

    // input conversions (batched: q/k/v, then Wq/Wk/Wv)
    cvt3_kernel<<<dim3(SEQ * DIM / 4 / 256, 3), blk>>>(q, k, v, q16, k16, v16,
                                                       SEQ * DIM / 4);
    cvt3_kernel<<<dim3(DIM * DIM / 4 / 256, 3), blk>>>(Wq, Wk, Wv, Wq16, Wk16, Wv16,
                                                       DIM * DIM / 4);

    // projections (1-term fp16), fp16 outputs
    dim3 gProj(DIM / 128, SEQ / 128);
    gemm_mma<1><<<gProj, blk, SMEM_SZ>>>(q16, Wq16, bq, nullptr, qp16, DIM, DIM, 1.0f);
    gemm_mma<1><<<gProj, blk, SMEM_SZ>>>(k16, Wk16, bk, nullptr, kp16, DIM, DIM, 1.0f);
    gemm_mma<2><<<gProj, blk, SMEM_SZ>>>(v16, Wv16, bv, nullptr, vt16, DIM, DIM, 1.0f);

    // scores = qp @ kp^T  (fp32 out, unscaled)
    dim3 gScore(SEQ / 128, SEQ / 128);
    gemm_mma<0><<<gScore, blk, SMEM_SZ>>>(qp16, kp16, nullptr, att, nullptr,
                                          SEQ, DIM, 1.0f);

    // softmax(scale * scores) + bias -> fp16 att
    softmax_bias_f16<<<SEQ, blk>>>(att, bias, a16, scale);

    // out = att @ vp  (vp accessed as vpT K-major)
    dim3 gOut(DIM / 128, SEQ / 128);
    gemm_mma<0><<<gOut, blk, SMEM_SZ>>>(a16, vt16, nullptr, out, nullptr,
                                        DIM, SEQ, 1.0f);
}